// round 10
// baseline (speedup 1.0000x reference)
#include <cuda_runtime.h>
#include <math.h>

#define NQ 512
#define NC 65536
#define DIN 768

// Scratch (static device globals).
__device__ float g_cfeatT[65 * NC];    // corpus: rows 0..63 hi, 64 = yn
__device__ float g_cfeatLo[64 * NC];
__device__ float g_qfeatT[69 * NQ];    // query: 0..63 hi, 64 xn, 65 beta, 66 w0, 67 w1*ln2^2, 68 w2
__device__ float g_qfeatLo[64 * NQ];
__device__ float g_wHi[64 * DIN];      // concatenated We/Wh/Ws tf32 hi
__device__ float g_wLo[64 * DIN];      // ... lo residual
__device__ float g_part[6 * NQ * 32];  // mlp split-K partials

// ---------------- helpers ----------------
__device__ __forceinline__ float f_rcp(float x)  { float r; asm("rcp.approx.f32 %0,%1;"  : "=f"(r) : "f"(x)); return r; }
__device__ __forceinline__ float f_sqrt(float x) { float r; asm("sqrt.approx.f32 %0,%1;" : "=f"(r) : "f"(x)); return r; }
__device__ __forceinline__ float f_lg2(float x)  { float r; asm("lg2.approx.f32 %0,%1;"  : "=f"(r) : "f"(x)); return r; }
__device__ __forceinline__ float tf32_rna(float x) {
    unsigned u; asm("cvt.rna.tf32.f32 %0,%1;" : "=r"(u) : "f"(x)); return __uint_as_float(u);
}
__device__ __forceinline__ void mma_tf32(float c[4], const unsigned a[4], const unsigned b[2]) {
    asm volatile(
        "mma.sync.aligned.m16n8k8.row.col.f32.tf32.tf32.f32 "
        "{%0,%1,%2,%3},{%4,%5,%6,%7},{%8,%9},{%0,%1,%2,%3};"
        : "+f"(c[0]), "+f"(c[1]), "+f"(c[2]), "+f"(c[3])
        : "r"(a[0]), "r"(a[1]), "r"(a[2]), "r"(a[3]), "r"(b[0]), "r"(b[1]));
}

// ---------------------------------------------------------------------------
// One-time W split: concatenated [64][768] tf32 hi/lo planes
// ---------------------------------------------------------------------------
__global__ void wsplit_kernel(const float* __restrict__ We,
                              const float* __restrict__ Wh,
                              const float* __restrict__ Ws,
                              float* __restrict__ wHi, float* __restrict__ wLo)
{
    int i = blockIdx.x * 256 + threadIdx.x;
    if (i >= 64 * DIN) return;
    int d = i / DIN;
    int k = i - d * DIN;
    float v = (d < 32) ? We[d * DIN + k]
            : (d < 48) ? Wh[(d - 32) * DIN + k]
                       : Ws[(d - 48) * DIN + k];
    float hi = tf32_rna(v);
    wHi[i] = hi;
    wLo[i] = tf32_rna(v - hi);
}

// ---------------------------------------------------------------------------
// Projection (tf32 MMA v3): 64 rows x 64 dims per CTA, 128 threads (4 warps),
// 4 CTAs/SM. W hi/lo precomputed. Coalesced psm epilogue (aliases staging).
// ---------------------------------------------------------------------------
__global__ __launch_bounds__(128, 4) void projmma_kernel(
    const float* __restrict__ X,
    const float* __restrict__ be, const float* __restrict__ bh,
    const float* __restrict__ bs, const float* __restrict__ scale_p,
    const float* __restrict__ wHi, const float* __restrict__ wLo,
    float* __restrict__ featT, float* __restrict__ featLo,
    int fstride, int is_query)
{
    __shared__ __align__(16) float sbuf[4608];           // 18.4 KB
    float (*xsh)[72] = (float(*)[72])(sbuf);             // 16 x 72
    float (*xsl)[72] = (float(*)[72])(sbuf + 1152);
    float (*wsh)[72] = (float(*)[72])(sbuf + 2304);
    float (*wsl)[72] = (float(*)[72])(sbuf + 3456);
    float (*psm)[69] = (float(*)[69])(sbuf);             // 64 x 69 (aliases)

    const int tid  = threadIdx.x;
    const int lane = tid & 31;
    const int warp = tid >> 5;       // 0..3 -> rows warp*16..
    const int gid  = lane >> 2;
    const int tig  = lane & 3;
    const int row0 = blockIdx.x * 64;

    const int rA = tid >> 1;         // 0..63 (x-row / w-dim)
    const int k8 = (tid & 1) * 8;    // 0 or 8

    const float* Xp  = X   + (size_t)(row0 + rA) * DIN + k8;
    const float* WHp = wHi + rA * DIN + k8;
    const float* WLp = wLo + rA * DIN + k8;

    float4 xv0 = *(const float4*)(Xp);
    float4 xv1 = *(const float4*)(Xp + 4);
    float4 wh0 = *(const float4*)(WHp);
    float4 wh1 = *(const float4*)(WHp + 4);
    float4 wl0 = *(const float4*)(WLp);
    float4 wl1 = *(const float4*)(WLp + 4);

    float acc[8][4];
#pragma unroll
    for (int t = 0; t < 8; t++)
#pragma unroll
        for (int m = 0; m < 4; m++) acc[t][m] = 0.f;

    for (int k0 = 0; k0 < DIN; k0 += 16) {
        __syncthreads();
        {
            const float* p0 = (const float*)&xv0;
            const float* p1 = (const float*)&xv1;
            const float* h0 = (const float*)&wh0;
            const float* h1 = (const float*)&wh1;
            const float* l0 = (const float*)&wl0;
            const float* l1 = (const float*)&wl1;
#pragma unroll
            for (int u = 0; u < 4; u++) {
                float a0 = tf32_rna(p0[u]);
                float a1 = tf32_rna(p1[u]);
                xsh[k8 + u][rA]     = a0;
                xsl[k8 + u][rA]     = tf32_rna(p0[u] - a0);
                xsh[k8 + 4 + u][rA] = a1;
                xsl[k8 + 4 + u][rA] = tf32_rna(p1[u] - a1);
                wsh[k8 + u][rA]     = h0[u];
                wsh[k8 + 4 + u][rA] = h1[u];
                wsl[k8 + u][rA]     = l0[u];
                wsl[k8 + 4 + u][rA] = l1[u];
            }
        }
        __syncthreads();
        if (k0 + 16 < DIN) {
            xv0 = *(const float4*)(Xp  + k0 + 16);
            xv1 = *(const float4*)(Xp  + k0 + 20);
            wh0 = *(const float4*)(WHp + k0 + 16);
            wh1 = *(const float4*)(WHp + k0 + 20);
            wl0 = *(const float4*)(WLp + k0 + 16);
            wl1 = *(const float4*)(WLp + k0 + 20);
        }
#pragma unroll
        for (int kc = 0; kc < 2; kc++) {
            const int ks = kc * 8;
            const int r = warp * 16 + gid;
            unsigned ah[4], al[4];
            ah[0] = __float_as_uint(xsh[ks + tig][r]);
            ah[1] = __float_as_uint(xsh[ks + tig][r + 8]);
            ah[2] = __float_as_uint(xsh[ks + tig + 4][r]);
            ah[3] = __float_as_uint(xsh[ks + tig + 4][r + 8]);
            al[0] = __float_as_uint(xsl[ks + tig][r]);
            al[1] = __float_as_uint(xsl[ks + tig][r + 8]);
            al[2] = __float_as_uint(xsl[ks + tig + 4][r]);
            al[3] = __float_as_uint(xsl[ks + tig + 4][r + 8]);
#pragma unroll
            for (int ct = 0; ct < 8; ct++) {
                const int cc = ct * 8 + gid;
                unsigned bh2[2], bl2[2];
                bh2[0] = __float_as_uint(wsh[ks + tig][cc]);
                bh2[1] = __float_as_uint(wsh[ks + tig + 4][cc]);
                bl2[0] = __float_as_uint(wsl[ks + tig][cc]);
                bl2[1] = __float_as_uint(wsl[ks + tig + 4][cc]);
                mma_tf32(acc[ct], ah, bh2);
                mma_tf32(acc[ct], ah, bl2);
                mma_tf32(acc[ct], al, bh2);
            }
        }
    }

    __syncthreads();   // staging dead; psm aliases it
    {
        const int r = warp * 16 + gid;
#pragma unroll
        for (int ct = 0; ct < 8; ct++) {
#pragma unroll
            for (int u = 0; u < 2; u++) {
                const int d = ct * 8 + 2 * tig + u;
                float bias = (d < 32) ? __ldg(be + d)
                           : (d < 48) ? __ldg(bh + d - 32)
                                      : __ldg(bs + d - 48);
                psm[r][d]     = acc[ct][u]     + bias;
                psm[r + 8][d] = acc[ct][2 + u] + bias;
            }
        }
    }
    __syncthreads();

    if (tid < 64) {
        const int r = tid;
        const float sc = *scale_p;
        float s2 = 0.f;
#pragma unroll
        for (int k = 0; k < 32; k++) { float v = psm[r][k]; s2 = fmaf(v, v, s2); }
        float inv = 1.0f / sqrtf(s2);
#pragma unroll
        for (int k = 0; k < 32; k++) psm[r][k] *= inv;
        float h2 = 0.f;
#pragma unroll
        for (int k = 32; k < 48; k++) { float v = psm[r][k] * sc; psm[r][k] = v; h2 = fmaf(v, v, h2); }
        float n  = fmaxf(sqrtf(h2), 1e-15f);
        float th = tanhf(n);
        float fac = th / n;
#pragma unroll
        for (int k = 32; k < 48; k++) psm[r][k] *= fac;
        psm[r][64] = th * th;                       // yn / xn
        if (is_query) psm[r][65] = 1.0f - th * th;  // beta
        float s3 = 0.f;
#pragma unroll
        for (int k = 48; k < 64; k++) { float v = psm[r][k]; s3 = fmaf(v, v, s3); }
        float inv3 = 1.0f / sqrtf(s3);
#pragma unroll
        for (int k = 48; k < 64; k++) psm[r][k] *= inv3;
    }
    __syncthreads();

    // features: hi/lo split, coalesced (64-wide rows)
    for (int i = tid; i < 64 * 64; i += 128) {
        int k = i >> 6, r = i & 63;
        float v = psm[r][k];
        float hi = tf32_rna(v);
        float lo = tf32_rna(v - hi);
        featT [(size_t)k * fstride + row0 + r] = hi;
        featLo[(size_t)k * fstride + row0 + r] = lo;
    }
    const int np = is_query ? 2 : 1;
    for (int i = tid; i < np * 64; i += 128) {
        int k = 64 + (i >> 6), r = i & 63;
        featT[(size_t)k * fstride + row0 + r] = psm[r][k];
    }
}

// ---------------------------------------------------------------------------
// Weight-MLP layer 1, split-K: partial x_q W1^T over K-chunk -> g_part
// grid = (8 row-blocks, 6 K-chunks), 256 threads
// ---------------------------------------------------------------------------
__global__ __launch_bounds__(256) void mlpq_part_kernel(
    const float* __restrict__ X, const float* __restrict__ W1,
    float* __restrict__ part)
{
    __shared__ __align__(16) float xs[16][68];
    __shared__ __align__(16) float ws[16][36];
    const int tid = threadIdx.x;
    const int r0 = (tid >> 3) * 2;
    const int d0 = (tid & 7) * 4;
    const int row0 = blockIdx.x * 64;
    const int kc   = blockIdx.y;            // 0..5
    const int kbeg = kc * 128;
    const int lr = tid >> 2;
    const int lk = (tid & 3) * 4;

    float acc[2][4] = {};
    for (int kk0 = 0; kk0 < 128; kk0 += 16) {
        const int k0 = kbeg + kk0;
        float4 xv = *(const float4*)(X + (size_t)(row0 + lr) * DIN + k0 + lk);
        float4 wv = make_float4(0.f, 0.f, 0.f, 0.f);
        if (tid < 128) wv = *(const float4*)(W1 + lr * DIN + k0 + lk);
        __syncthreads();
        xs[lk + 0][lr] = xv.x; xs[lk + 1][lr] = xv.y;
        xs[lk + 2][lr] = xv.z; xs[lk + 3][lr] = xv.w;
        if (tid < 128) {
            ws[lk + 0][lr] = wv.x; ws[lk + 1][lr] = wv.y;
            ws[lk + 2][lr] = wv.z; ws[lk + 3][lr] = wv.w;
        }
        __syncthreads();
#pragma unroll
        for (int kk = 0; kk < 16; kk++) {
            float a0 = xs[kk][r0];
            float a1 = xs[kk][r0 + 1];
            float4 b4 = *(const float4*)&ws[kk][d0];
            float bv[4] = {b4.x, b4.y, b4.z, b4.w};
#pragma unroll
            for (int j = 0; j < 4; j++) {
                acc[0][j] = fmaf(a0, bv[j], acc[0][j]);
                acc[1][j] = fmaf(a1, bv[j], acc[1][j]);
            }
        }
    }
    float* dst = part + (size_t)kc * NQ * 32;
#pragma unroll
    for (int i = 0; i < 2; i++)
#pragma unroll
        for (int j = 0; j < 4; j++)
            dst[(size_t)(row0 + r0 + i) * 32 + d0 + j] = acc[i][j];
}

// ---------------------------------------------------------------------------
// Weight-MLP finish: sum partials + b1, relu, layer2 + softplus -> qfT 66..68
// ---------------------------------------------------------------------------
__global__ __launch_bounds__(256) void mlpq_fin_kernel(
    const float* __restrict__ part, const float* __restrict__ b1,
    const float* __restrict__ W2, const float* __restrict__ b2,
    float* __restrict__ qfT)
{
    const int q = blockIdx.x * 256 + threadIdx.x;
    if (q >= NQ) return;
    float y[32];
#pragma unroll
    for (int d = 0; d < 32; d += 4) {
        float4 s = *(const float4*)(part + (size_t)q * 32 + d);
#pragma unroll
        for (int kc = 1; kc < 6; kc++) {
            float4 p = *(const float4*)(part + (size_t)kc * NQ * 32 + (size_t)q * 32 + d);
            s.x += p.x; s.y += p.y; s.z += p.z; s.w += p.w;
        }
        y[d]     = fmaxf(s.x + __ldg(b1 + d),     0.f);
        y[d + 1] = fmaxf(s.y + __ldg(b1 + d + 1), 0.f);
        y[d + 2] = fmaxf(s.z + __ldg(b1 + d + 2), 0.f);
        y[d + 3] = fmaxf(s.w + __ldg(b1 + d + 3), 0.f);
    }
    float z0 = b2[0], z1 = b2[1], z2 = b2[2];
#pragma unroll
    for (int k = 0; k < 32; k++) {
        z0 = fmaf(y[k], __ldg(W2 + k),      z0);
        z1 = fmaf(y[k], __ldg(W2 + 32 + k), z1);
        z2 = fmaf(y[k], __ldg(W2 + 64 + k), z2);
    }
    float sp0 = fmaxf(z0, 0.f) + log1pf(expf(-fabsf(z0)));
    float sp1 = fmaxf(z1, 0.f) + log1pf(expf(-fabsf(z1)));
    float sp2 = fmaxf(z2, 0.f) + log1pf(expf(-fabsf(z2)));
    qfT[(size_t)66 * NQ + q] = sp0;
    qfT[(size_t)67 * NQ + q] = sp1 * 0.4804530139182014f;  // fold ln2^2
    qfT[(size_t)68 * NQ + q] = sp2;
}

// ---------------------------------------------------------------------------
// Pairwise kernel: 64q x 128c per CTA, 8 warps of 32x32, tf32 MMA split hi/lo
// (conflict-free pads 72 / 136)
// ---------------------------------------------------------------------------
__global__ __launch_bounds__(256, 2) void pair_kernel(
    const float* __restrict__ qfT, const float* __restrict__ qfLo,
    const float* __restrict__ cfT, const float* __restrict__ cfLo,
    float* __restrict__ out)
{
    __shared__ __align__(16) float sqh[16][72], sql[16][72];
    __shared__ __align__(16) float sch[16][136], sclo[16][136];
    __shared__ float qxn[64], qbt[64], qw0[64], qw1[64], qw2[64], cyn[128];

    const int tid  = threadIdx.x;
    const int lane = tid & 31;
    const int warp = tid >> 5;
    const int gid  = lane >> 2;
    const int tig  = lane & 3;
    const int qw   = (warp >> 2) * 32;
    const int cw   = (warp & 3) * 32;

    const int q0 = blockIdx.y * 64;
    const int c0 = blockIdx.x * 128;

    if (tid < 64) {
        qxn[tid] = qfT[(size_t)64 * NQ + q0 + tid];
        qbt[tid] = qfT[(size_t)65 * NQ + q0 + tid];
        qw0[tid] = qfT[(size_t)66 * NQ + q0 + tid];
        qw1[tid] = qfT[(size_t)67 * NQ + q0 + tid];
        qw2[tid] = qfT[(size_t)68 * NQ + q0 + tid];
    } else if (tid < 192) {
        const int r = tid - 64;
        cyn[r] = cfT[(size_t)64 * NC + c0 + r];
    }

    auto stage = [&](int off) {
        {
            const int row = tid >> 4;
            const int c4  = (tid & 15) * 4;
            *(float4*)&sqh[row][c4] = *(const float4*)(qfT  + (size_t)(off + row) * NQ + q0 + c4);
            *(float4*)&sql[row][c4] = *(const float4*)(qfLo + (size_t)(off + row) * NQ + q0 + c4);
        }
        for (int t = tid; t < 512; t += 256) {
            const int row = t >> 5;
            const int c4  = (t & 31) * 4;
            *(float4*)&sch [row][c4] = *(const float4*)(cfT  + (size_t)(off + row) * NC + c0 + c4);
            *(float4*)&sclo[row][c4] = *(const float4*)(cfLo + (size_t)(off + row) * NC + c0 + c4);
        }
    };

    auto seg_mma = [&](float acc[8][4]) {
#pragma unroll
        for (int kc = 0; kc < 2; kc++) {
            const int k0 = kc * 8;
            unsigned bh[4][2], bl[4][2];
#pragma unroll
            for (int ct = 0; ct < 4; ct++) {
                const int cc = cw + ct * 8 + gid;
                bh[ct][0] = __float_as_uint(sch [k0 + tig][cc]);
                bh[ct][1] = __float_as_uint(sch [k0 + tig + 4][cc]);
                bl[ct][0] = __float_as_uint(sclo[k0 + tig][cc]);
                bl[ct][1] = __float_as_uint(sclo[k0 + tig + 4][cc]);
            }
#pragma unroll
            for (int qt = 0; qt < 2; qt++) {
                const int r = qw + qt * 16 + gid;
                unsigned ah[4], al[4];
                ah[0] = __float_as_uint(sqh[k0 + tig][r]);
                ah[1] = __float_as_uint(sqh[k0 + tig][r + 8]);
                ah[2] = __float_as_uint(sqh[k0 + tig + 4][r]);
                ah[3] = __float_as_uint(sqh[k0 + tig + 4][r + 8]);
                al[0] = __float_as_uint(sql[k0 + tig][r]);
                al[1] = __float_as_uint(sql[k0 + tig][r + 8]);
                al[2] = __float_as_uint(sql[k0 + tig + 4][r]);
                al[3] = __float_as_uint(sql[k0 + tig + 4][r + 8]);
#pragma unroll
                for (int ct = 0; ct < 4; ct++) {
                    float* a = acc[qt * 4 + ct];
                    mma_tf32(a, ah, bh[ct]);
                    mma_tf32(a, ah, bl[ct]);
                    mma_tf32(a, al, bh[ct]);
                }
            }
        }
    };

    float tot[8][4];
    float acc[8][4];

    // ================= phase e =================
#pragma unroll
    for (int t = 0; t < 8; t++)
#pragma unroll
        for (int m = 0; m < 4; m++) acc[t][m] = 0.f;
    stage(0);
    __syncthreads();
    seg_mma(acc);
    __syncthreads();
    stage(16);
    __syncthreads();
    seg_mma(acc);
#pragma unroll
    for (int qt = 0; qt < 2; qt++) {
        const int lqA = qw + qt * 16 + gid;
        const float wA = qw0[lqA], wB = qw0[lqA + 8];
#pragma unroll
        for (int ct = 0; ct < 4; ct++) {
            const int t = qt * 4 + ct;
            tot[t][0] = wA * (2.f - 2.f * acc[t][0]);
            tot[t][1] = wA * (2.f - 2.f * acc[t][1]);
            tot[t][2] = wB * (2.f - 2.f * acc[t][2]);
            tot[t][3] = wB * (2.f - 2.f * acc[t][3]);
        }
    }

    // ================= phase h =================
#pragma unroll
    for (int t = 0; t < 8; t++)
#pragma unroll
        for (int m = 0; m < 4; m++) acc[t][m] = 0.f;
    __syncthreads();
    stage(32);
    __syncthreads();
    seg_mma(acc);
#pragma unroll
    for (int qt = 0; qt < 2; qt++) {
        const int lqA = qw + qt * 16 + gid;
#pragma unroll
        for (int half = 0; half < 2; half++) {
            const int lq = lqA + half * 8;
            const float xn = qxn[lq];
            const float bt = qbt[lq];
            const float nb = -2.f * bt;
            const float bb = bt * bt;
            const float w1 = qw1[lq];
#pragma unroll
            for (int ct = 0; ct < 4; ct++) {
                const int t = qt * 4 + ct;
                const int lc = cw + ct * 8 + 2 * tig;
#pragma unroll
                for (int m = 0; m < 2; m++) {
                    const float dh = acc[t][half * 2 + m];
                    const float yn = cyn[lc + m];
                    float s1 = fmaf(-2.f, dh, 1.f);
                    float alpha = s1 + yn;
                    float num = fmaf(alpha, fmaf(alpha, xn, nb * dh), bb * yn);
                    float den = fmaxf(fmaf(xn, yn, s1), 1e-15f);
                    float tv = f_sqrt(fmaxf(num, 0.f)) * f_rcp(den);
                    tv = fminf(tv, 0.99999994f);
                    float L = f_lg2((1.f + tv) * f_rcp(1.f - tv));
                    tot[t][half * 2 + m] = fmaf(w1, L * L, tot[t][half * 2 + m]);
                }
            }
        }
    }

    // ================= phase s =================
#pragma unroll
    for (int t = 0; t < 8; t++)
#pragma unroll
        for (int m = 0; m < 4; m++) acc[t][m] = 0.f;
    __syncthreads();
    stage(48);
    __syncthreads();
    seg_mma(acc);
#pragma unroll
    for (int qt = 0; qt < 2; qt++) {
        const int lqA = qw + qt * 16 + gid;
#pragma unroll
        for (int half = 0; half < 2; half++) {
            const int lq = lqA + half * 8;
            const float w2 = qw2[lq];
#pragma unroll
            for (int ct = 0; ct < 4; ct++) {
                const int t = qt * 4 + ct;
#pragma unroll
                for (int m = 0; m < 2; m++) {
                    const float d = acc[t][half * 2 + m];
                    float ad = fminf(fabsf(d), 1.f);
                    float sq = f_sqrt(fmaxf(1.f - ad, 0.f));
                    float p = -0.0012624911f;
                    p = fmaf(p, ad,  0.0066700901f);
                    p = fmaf(p, ad, -0.0170881256f);
                    p = fmaf(p, ad,  0.0308918810f);
                    p = fmaf(p, ad, -0.0501743046f);
                    p = fmaf(p, ad,  0.0889789874f);
                    p = fmaf(p, ad, -0.2145988016f);
                    p = fmaf(p, ad,  1.5707963050f);
                    float r = sq * p;
                    float a = (d >= 0.f) ? r : 3.14159265358979f - r;
                    tot[t][half * 2 + m] = fmaf(w2, a * a, tot[t][half * 2 + m]);
                }
            }
        }
    }

    // ================= store -total =================
#pragma unroll
    for (int qt = 0; qt < 2; qt++) {
        const int lqA = qw + qt * 16 + gid;
#pragma unroll
        for (int ct = 0; ct < 4; ct++) {
            const int t = qt * 4 + ct;
            const int lc = cw + ct * 8 + 2 * tig;
            float2 oA = make_float2(-tot[t][0], -tot[t][1]);
            float2 oB = make_float2(-tot[t][2], -tot[t][3]);
            *(float2*)(out + (size_t)(q0 + lqA) * NC + c0 + lc)     = oA;
            *(float2*)(out + (size_t)(q0 + lqA + 8) * NC + c0 + lc) = oB;
        }
    }
}

// ---------------------------------------------------------------------------
extern "C" void kernel_launch(void* const* d_in, const int* in_sizes, int n_in,
                              void* d_out, int out_size)
{
    const float* x_q  = (const float*)d_in[0];
    const float* x_c  = (const float*)d_in[1];
    const float* We   = (const float*)d_in[2];
    const float* be   = (const float*)d_in[3];
    const float* Wh   = (const float*)d_in[4];
    const float* bh   = (const float*)d_in[5];
    const float* Ws   = (const float*)d_in[6];
    const float* bs   = (const float*)d_in[7];
    const float* scl  = (const float*)d_in[8];
    const float* W1   = (const float*)d_in[9];
    const float* b1   = (const float*)d_in[10];
    const float* W2   = (const float*)d_in[11];
    const float* b2   = (const float*)d_in[12];
    float* out = (float*)d_out;

    float *cfT, *cfLo, *qfT, *qfLo, *wHi, *wLo, *part;
    cudaGetSymbolAddress((void**)&cfT,  g_cfeatT);
    cudaGetSymbolAddress((void**)&cfLo, g_cfeatLo);
    cudaGetSymbolAddress((void**)&qfT,  g_qfeatT);
    cudaGetSymbolAddress((void**)&qfLo, g_qfeatLo);
    cudaGetSymbolAddress((void**)&wHi,  g_wHi);
    cudaGetSymbolAddress((void**)&wLo,  g_wLo);
    cudaGetSymbolAddress((void**)&part, g_part);

    wsplit_kernel<<<(64 * DIN + 255) / 256, 256>>>(We, Wh, Ws, wHi, wLo);
    projmma_kernel<<<NC / 64, 128>>>(x_c, be, bh, bs, scl, wHi, wLo, cfT, cfLo, NC, 0);
    projmma_kernel<<<NQ / 64, 128>>>(x_q, be, bh, bs, scl, wHi, wLo, qfT, qfLo, NQ, 1);
    mlpq_part_kernel<<<dim3(NQ / 64, 6), 256>>>(x_q, W1, part);
    mlpq_fin_kernel<<<NQ / 256, 256>>>(part, b1, W2, b2, qfT);
    pair_kernel<<<dim3(NC / 128, NQ / 64), 256>>>(qfT, qfLo, cfT, cfLo, out);
}

// round 11
// speedup vs baseline: 1.5033x; 1.5033x over previous
#include <cuda_runtime.h>
#include <math.h>

#define NQ 512
#define NC 65536
#define DIN 768

// Scratch (static device globals).
__device__ float g_cfeatT[65 * NC];    // corpus: rows 0..63 hi, 64 = yn
__device__ float g_cfeatLo[64 * NC];
__device__ float g_qfeatT[69 * NQ];    // query: 0..63 hi, 64 xn, 65 beta, 66 w0, 67 w1*ln2^2, 68 w2
__device__ float g_qfeatLo[64 * NQ];
__device__ float g_wHi[64 * DIN];      // concatenated We/Wh/Ws tf32 hi
__device__ float g_wLo[64 * DIN];      // ... lo residual
__device__ float g_part[6 * NQ * 32];  // mlp split-K partials

// ---------------- helpers ----------------
__device__ __forceinline__ float f_rcp(float x)  { float r; asm("rcp.approx.f32 %0,%1;"  : "=f"(r) : "f"(x)); return r; }
__device__ __forceinline__ float f_sqrt(float x) { float r; asm("sqrt.approx.f32 %0,%1;" : "=f"(r) : "f"(x)); return r; }
__device__ __forceinline__ float f_lg2(float x)  { float r; asm("lg2.approx.f32 %0,%1;"  : "=f"(r) : "f"(x)); return r; }
__device__ __forceinline__ float tf32_rna(float x) {
    unsigned u; asm("cvt.rna.tf32.f32 %0,%1;" : "=r"(u) : "f"(x)); return __uint_as_float(u);
}
__device__ __forceinline__ void mma_tf32(float c[4], const unsigned a[4], const unsigned b[2]) {
    asm volatile(
        "mma.sync.aligned.m16n8k8.row.col.f32.tf32.tf32.f32 "
        "{%0,%1,%2,%3},{%4,%5,%6,%7},{%8,%9},{%0,%1,%2,%3};"
        : "+f"(c[0]), "+f"(c[1]), "+f"(c[2]), "+f"(c[3])
        : "r"(a[0]), "r"(a[1]), "r"(a[2]), "r"(a[3]), "r"(b[0]), "r"(b[1]));
}

// ---------------------------------------------------------------------------
// One-time W split: concatenated [64][768] tf32 hi/lo planes
// ---------------------------------------------------------------------------
__global__ void wsplit_kernel(const float* __restrict__ We,
                              const float* __restrict__ Wh,
                              const float* __restrict__ Ws,
                              float* __restrict__ wHi, float* __restrict__ wLo)
{
    int i = blockIdx.x * 256 + threadIdx.x;
    if (i >= 64 * DIN) return;
    int d = i / DIN;
    int k = i - d * DIN;
    float v = (d < 32) ? We[d * DIN + k]
            : (d < 48) ? Wh[(d - 32) * DIN + k]
                       : Ws[(d - 48) * DIN + k];
    float hi = tf32_rna(v);
    wHi[i] = hi;
    wLo[i] = tf32_rna(v - hi);
}

// ---------------------------------------------------------------------------
// Projection (tf32 MMA v3): 64 rows x 64 dims per CTA, 128 threads (4 warps),
// 4 CTAs/SM. W hi/lo precomputed. Coalesced psm epilogue (aliases staging).
// ---------------------------------------------------------------------------
__global__ __launch_bounds__(128, 4) void projmma_kernel(
    const float* __restrict__ X,
    const float* __restrict__ be, const float* __restrict__ bh,
    const float* __restrict__ bs, const float* __restrict__ scale_p,
    const float* __restrict__ wHi, const float* __restrict__ wLo,
    float* __restrict__ featT, float* __restrict__ featLo,
    int fstride, int is_query)
{
    __shared__ __align__(16) float sbuf[4608];           // 18.4 KB
    float (*xsh)[72] = (float(*)[72])(sbuf);             // 16 x 72
    float (*xsl)[72] = (float(*)[72])(sbuf + 1152);
    float (*wsh)[72] = (float(*)[72])(sbuf + 2304);
    float (*wsl)[72] = (float(*)[72])(sbuf + 3456);
    float (*psm)[69] = (float(*)[69])(sbuf);             // 64 x 69 (aliases)

    const int tid  = threadIdx.x;
    const int lane = tid & 31;
    const int warp = tid >> 5;       // 0..3 -> rows warp*16..
    const int gid  = lane >> 2;
    const int tig  = lane & 3;
    const int row0 = blockIdx.x * 64;

    const int rA = tid >> 1;         // 0..63 (x-row / w-dim)
    const int k8 = (tid & 1) * 8;    // 0 or 8

    const float* Xp  = X   + (size_t)(row0 + rA) * DIN + k8;
    const float* WHp = wHi + rA * DIN + k8;
    const float* WLp = wLo + rA * DIN + k8;

    float4 xv0 = *(const float4*)(Xp);
    float4 xv1 = *(const float4*)(Xp + 4);
    float4 wh0 = *(const float4*)(WHp);
    float4 wh1 = *(const float4*)(WHp + 4);
    float4 wl0 = *(const float4*)(WLp);
    float4 wl1 = *(const float4*)(WLp + 4);

    float acc[8][4];
#pragma unroll
    for (int t = 0; t < 8; t++)
#pragma unroll
        for (int m = 0; m < 4; m++) acc[t][m] = 0.f;

    for (int k0 = 0; k0 < DIN; k0 += 16) {
        __syncthreads();
        {
            const float* p0 = (const float*)&xv0;
            const float* p1 = (const float*)&xv1;
            const float* h0 = (const float*)&wh0;
            const float* h1 = (const float*)&wh1;
            const float* l0 = (const float*)&wl0;
            const float* l1 = (const float*)&wl1;
#pragma unroll
            for (int u = 0; u < 4; u++) {
                float a0 = tf32_rna(p0[u]);
                float a1 = tf32_rna(p1[u]);
                xsh[k8 + u][rA]     = a0;
                xsl[k8 + u][rA]     = tf32_rna(p0[u] - a0);
                xsh[k8 + 4 + u][rA] = a1;
                xsl[k8 + 4 + u][rA] = tf32_rna(p1[u] - a1);
                wsh[k8 + u][rA]     = h0[u];
                wsh[k8 + 4 + u][rA] = h1[u];
                wsl[k8 + u][rA]     = l0[u];
                wsl[k8 + 4 + u][rA] = l1[u];
            }
        }
        __syncthreads();
        if (k0 + 16 < DIN) {
            xv0 = *(const float4*)(Xp  + k0 + 16);
            xv1 = *(const float4*)(Xp  + k0 + 20);
            wh0 = *(const float4*)(WHp + k0 + 16);
            wh1 = *(const float4*)(WHp + k0 + 20);
            wl0 = *(const float4*)(WLp + k0 + 16);
            wl1 = *(const float4*)(WLp + k0 + 20);
        }
#pragma unroll
        for (int kc = 0; kc < 2; kc++) {
            const int ks = kc * 8;
            const int r = warp * 16 + gid;
            unsigned ah[4], al[4];
            ah[0] = __float_as_uint(xsh[ks + tig][r]);
            ah[1] = __float_as_uint(xsh[ks + tig][r + 8]);
            ah[2] = __float_as_uint(xsh[ks + tig + 4][r]);
            ah[3] = __float_as_uint(xsh[ks + tig + 4][r + 8]);
            al[0] = __float_as_uint(xsl[ks + tig][r]);
            al[1] = __float_as_uint(xsl[ks + tig][r + 8]);
            al[2] = __float_as_uint(xsl[ks + tig + 4][r]);
            al[3] = __float_as_uint(xsl[ks + tig + 4][r + 8]);
#pragma unroll
            for (int ct = 0; ct < 8; ct++) {
                const int cc = ct * 8 + gid;
                unsigned bh2[2], bl2[2];
                bh2[0] = __float_as_uint(wsh[ks + tig][cc]);
                bh2[1] = __float_as_uint(wsh[ks + tig + 4][cc]);
                bl2[0] = __float_as_uint(wsl[ks + tig][cc]);
                bl2[1] = __float_as_uint(wsl[ks + tig + 4][cc]);
                mma_tf32(acc[ct], ah, bh2);
                mma_tf32(acc[ct], ah, bl2);
                mma_tf32(acc[ct], al, bh2);
            }
        }
    }

    __syncthreads();   // staging dead; psm aliases it
    {
        const int r = warp * 16 + gid;
#pragma unroll
        for (int ct = 0; ct < 8; ct++) {
#pragma unroll
            for (int u = 0; u < 2; u++) {
                const int d = ct * 8 + 2 * tig + u;
                float bias = (d < 32) ? __ldg(be + d)
                           : (d < 48) ? __ldg(bh + d - 32)
                                      : __ldg(bs + d - 48);
                psm[r][d]     = acc[ct][u]     + bias;
                psm[r + 8][d] = acc[ct][2 + u] + bias;
            }
        }
    }
    __syncthreads();

    if (tid < 64) {
        const int r = tid;
        const float sc = *scale_p;
        float s2 = 0.f;
#pragma unroll
        for (int k = 0; k < 32; k++) { float v = psm[r][k]; s2 = fmaf(v, v, s2); }
        float inv = 1.0f / sqrtf(s2);
#pragma unroll
        for (int k = 0; k < 32; k++) psm[r][k] *= inv;
        float h2 = 0.f;
#pragma unroll
        for (int k = 32; k < 48; k++) { float v = psm[r][k] * sc; psm[r][k] = v; h2 = fmaf(v, v, h2); }
        float n  = fmaxf(sqrtf(h2), 1e-15f);
        float th = tanhf(n);
        float fac = th / n;
#pragma unroll
        for (int k = 32; k < 48; k++) psm[r][k] *= fac;
        psm[r][64] = th * th;                       // yn / xn
        if (is_query) psm[r][65] = 1.0f - th * th;  // beta
        float s3 = 0.f;
#pragma unroll
        for (int k = 48; k < 64; k++) { float v = psm[r][k]; s3 = fmaf(v, v, s3); }
        float inv3 = 1.0f / sqrtf(s3);
#pragma unroll
        for (int k = 48; k < 64; k++) psm[r][k] *= inv3;
    }
    __syncthreads();

    // features: hi/lo split, coalesced (64-wide rows)
    for (int i = tid; i < 64 * 64; i += 128) {
        int k = i >> 6, r = i & 63;
        float v = psm[r][k];
        float hi = tf32_rna(v);
        float lo = tf32_rna(v - hi);
        featT [(size_t)k * fstride + row0 + r] = hi;
        featLo[(size_t)k * fstride + row0 + r] = lo;
    }
    const int np = is_query ? 2 : 1;
    for (int i = tid; i < np * 64; i += 128) {
        int k = 64 + (i >> 6), r = i & 63;
        featT[(size_t)k * fstride + row0 + r] = psm[r][k];
    }
}

// ---------------------------------------------------------------------------
// Weight-MLP layer 1, split-K with register prefetch: partials -> g_part
// grid = (8 row-blocks, 6 K-chunks), 256 threads
// ---------------------------------------------------------------------------
__global__ __launch_bounds__(256) void mlpq_part_kernel(
    const float* __restrict__ X, const float* __restrict__ W1,
    float* __restrict__ part)
{
    __shared__ __align__(16) float xs[16][68];
    __shared__ __align__(16) float ws[16][36];
    const int tid = threadIdx.x;
    const int r0 = (tid >> 3) * 2;
    const int d0 = (tid & 7) * 4;
    const int row0 = blockIdx.x * 64;
    const int kc   = blockIdx.y;            // 0..5
    const int kbeg = kc * 128;
    const int lr = tid >> 2;
    const int lk = (tid & 3) * 4;

    const float* Xp = X + (size_t)(row0 + lr) * DIN + kbeg + lk;
    const float* Wp = W1 + lr * DIN + kbeg + lk;

    float4 xv = *(const float4*)(Xp);
    float4 wv = make_float4(0.f, 0.f, 0.f, 0.f);
    if (tid < 128) wv = *(const float4*)(Wp);

    float acc[2][4] = {};
    for (int kk0 = 0; kk0 < 128; kk0 += 16) {
        __syncthreads();
        xs[lk + 0][lr] = xv.x; xs[lk + 1][lr] = xv.y;
        xs[lk + 2][lr] = xv.z; xs[lk + 3][lr] = xv.w;
        if (tid < 128) {
            ws[lk + 0][lr] = wv.x; ws[lk + 1][lr] = wv.y;
            ws[lk + 2][lr] = wv.z; ws[lk + 3][lr] = wv.w;
        }
        __syncthreads();
        if (kk0 + 16 < 128) {
            xv = *(const float4*)(Xp + kk0 + 16);
            if (tid < 128) wv = *(const float4*)(Wp + kk0 + 16);
        }
#pragma unroll
        for (int kk = 0; kk < 16; kk++) {
            float a0 = xs[kk][r0];
            float a1 = xs[kk][r0 + 1];
            float4 b4 = *(const float4*)&ws[kk][d0];
            float bv[4] = {b4.x, b4.y, b4.z, b4.w};
#pragma unroll
            for (int j = 0; j < 4; j++) {
                acc[0][j] = fmaf(a0, bv[j], acc[0][j]);
                acc[1][j] = fmaf(a1, bv[j], acc[1][j]);
            }
        }
    }
    float* dst = part + (size_t)kc * NQ * 32;
#pragma unroll
    for (int i = 0; i < 2; i++)
#pragma unroll
        for (int j = 0; j < 4; j++)
            dst[(size_t)(row0 + r0 + i) * 32 + d0 + j] = acc[i][j];
}

// ---------------------------------------------------------------------------
// Weight-MLP finish: sum partials + b1, relu, layer2 + softplus -> qfT 66..68
// ---------------------------------------------------------------------------
__global__ __launch_bounds__(256) void mlpq_fin_kernel(
    const float* __restrict__ part, const float* __restrict__ b1,
    const float* __restrict__ W2, const float* __restrict__ b2,
    float* __restrict__ qfT)
{
    const int q = blockIdx.x * 256 + threadIdx.x;
    if (q >= NQ) return;
    float y[32];
#pragma unroll
    for (int d = 0; d < 32; d += 4) {
        float4 s = *(const float4*)(part + (size_t)q * 32 + d);
#pragma unroll
        for (int kc = 1; kc < 6; kc++) {
            float4 p = *(const float4*)(part + (size_t)kc * NQ * 32 + (size_t)q * 32 + d);
            s.x += p.x; s.y += p.y; s.z += p.z; s.w += p.w;
        }
        y[d]     = fmaxf(s.x + __ldg(b1 + d),     0.f);
        y[d + 1] = fmaxf(s.y + __ldg(b1 + d + 1), 0.f);
        y[d + 2] = fmaxf(s.z + __ldg(b1 + d + 2), 0.f);
        y[d + 3] = fmaxf(s.w + __ldg(b1 + d + 3), 0.f);
    }
    float z0 = b2[0], z1 = b2[1], z2 = b2[2];
#pragma unroll
    for (int k = 0; k < 32; k++) {
        z0 = fmaf(y[k], __ldg(W2 + k),      z0);
        z1 = fmaf(y[k], __ldg(W2 + 32 + k), z1);
        z2 = fmaf(y[k], __ldg(W2 + 64 + k), z2);
    }
    float sp0 = fmaxf(z0, 0.f) + log1pf(expf(-fabsf(z0)));
    float sp1 = fmaxf(z1, 0.f) + log1pf(expf(-fabsf(z1)));
    float sp2 = fmaxf(z2, 0.f) + log1pf(expf(-fabsf(z2)));
    qfT[(size_t)66 * NQ + q] = sp0;
    qfT[(size_t)67 * NQ + q] = sp1 * 0.4804530139182014f;  // fold ln2^2
    qfT[(size_t)68 * NQ + q] = sp2;
}

// ---------------------------------------------------------------------------
// Pairwise kernel: 64q x 128c per CTA, 8 warps of 32x32, tf32 MMA split hi/lo
// (conflict-free pads 72 / 136)
// ---------------------------------------------------------------------------
__global__ __launch_bounds__(256, 2) void pair_kernel(
    const float* __restrict__ qfT, const float* __restrict__ qfLo,
    const float* __restrict__ cfT, const float* __restrict__ cfLo,
    float* __restrict__ out)
{
    __shared__ __align__(16) float sqh[16][72], sql[16][72];
    __shared__ __align__(16) float sch[16][136], sclo[16][136];
    __shared__ float qxn[64], qbt[64], qw0[64], qw1[64], qw2[64], cyn[128];

    const int tid  = threadIdx.x;
    const int lane = tid & 31;
    const int warp = tid >> 5;
    const int gid  = lane >> 2;
    const int tig  = lane & 3;
    const int qw   = (warp >> 2) * 32;
    const int cw   = (warp & 3) * 32;

    const int q0 = blockIdx.y * 64;
    const int c0 = blockIdx.x * 128;

    if (tid < 64) {
        qxn[tid] = qfT[(size_t)64 * NQ + q0 + tid];
        qbt[tid] = qfT[(size_t)65 * NQ + q0 + tid];
        qw0[tid] = qfT[(size_t)66 * NQ + q0 + tid];
        qw1[tid] = qfT[(size_t)67 * NQ + q0 + tid];
        qw2[tid] = qfT[(size_t)68 * NQ + q0 + tid];
    } else if (tid < 192) {
        const int r = tid - 64;
        cyn[r] = cfT[(size_t)64 * NC + c0 + r];
    }

    auto stage = [&](int off) {
        {
            const int row = tid >> 4;
            const int c4  = (tid & 15) * 4;
            *(float4*)&sqh[row][c4] = *(const float4*)(qfT  + (size_t)(off + row) * NQ + q0 + c4);
            *(float4*)&sql[row][c4] = *(const float4*)(qfLo + (size_t)(off + row) * NQ + q0 + c4);
        }
        for (int t = tid; t < 512; t += 256) {
            const int row = t >> 5;
            const int c4  = (t & 31) * 4;
            *(float4*)&sch [row][c4] = *(const float4*)(cfT  + (size_t)(off + row) * NC + c0 + c4);
            *(float4*)&sclo[row][c4] = *(const float4*)(cfLo + (size_t)(off + row) * NC + c0 + c4);
        }
    };

    auto seg_mma = [&](float acc[8][4]) {
#pragma unroll
        for (int kc = 0; kc < 2; kc++) {
            const int k0 = kc * 8;
            unsigned bh[4][2], bl[4][2];
#pragma unroll
            for (int ct = 0; ct < 4; ct++) {
                const int cc = cw + ct * 8 + gid;
                bh[ct][0] = __float_as_uint(sch [k0 + tig][cc]);
                bh[ct][1] = __float_as_uint(sch [k0 + tig + 4][cc]);
                bl[ct][0] = __float_as_uint(sclo[k0 + tig][cc]);
                bl[ct][1] = __float_as_uint(sclo[k0 + tig + 4][cc]);
            }
#pragma unroll
            for (int qt = 0; qt < 2; qt++) {
                const int r = qw + qt * 16 + gid;
                unsigned ah[4], al[4];
                ah[0] = __float_as_uint(sqh[k0 + tig][r]);
                ah[1] = __float_as_uint(sqh[k0 + tig][r + 8]);
                ah[2] = __float_as_uint(sqh[k0 + tig + 4][r]);
                ah[3] = __float_as_uint(sqh[k0 + tig + 4][r + 8]);
                al[0] = __float_as_uint(sql[k0 + tig][r]);
                al[1] = __float_as_uint(sql[k0 + tig][r + 8]);
                al[2] = __float_as_uint(sql[k0 + tig + 4][r]);
                al[3] = __float_as_uint(sql[k0 + tig + 4][r + 8]);
#pragma unroll
                for (int ct = 0; ct < 4; ct++) {
                    float* a = acc[qt * 4 + ct];
                    mma_tf32(a, ah, bh[ct]);
                    mma_tf32(a, ah, bl[ct]);
                    mma_tf32(a, al, bh[ct]);
                }
            }
        }
    };

    float tot[8][4];
    float acc[8][4];

    // ================= phase e =================
#pragma unroll
    for (int t = 0; t < 8; t++)
#pragma unroll
        for (int m = 0; m < 4; m++) acc[t][m] = 0.f;
    stage(0);
    __syncthreads();
    seg_mma(acc);
    __syncthreads();
    stage(16);
    __syncthreads();
    seg_mma(acc);
#pragma unroll
    for (int qt = 0; qt < 2; qt++) {
        const int lqA = qw + qt * 16 + gid;
        const float wA = qw0[lqA], wB = qw0[lqA + 8];
#pragma unroll
        for (int ct = 0; ct < 4; ct++) {
            const int t = qt * 4 + ct;
            tot[t][0] = wA * (2.f - 2.f * acc[t][0]);
            tot[t][1] = wA * (2.f - 2.f * acc[t][1]);
            tot[t][2] = wB * (2.f - 2.f * acc[t][2]);
            tot[t][3] = wB * (2.f - 2.f * acc[t][3]);
        }
    }

    // ================= phase h =================
#pragma unroll
    for (int t = 0; t < 8; t++)
#pragma unroll
        for (int m = 0; m < 4; m++) acc[t][m] = 0.f;
    __syncthreads();
    stage(32);
    __syncthreads();
    seg_mma(acc);
#pragma unroll
    for (int qt = 0; qt < 2; qt++) {
        const int lqA = qw + qt * 16 + gid;
#pragma unroll
        for (int half = 0; half < 2; half++) {
            const int lq = lqA + half * 8;
            const float xn = qxn[lq];
            const float bt = qbt[lq];
            const float nb = -2.f * bt;
            const float bb = bt * bt;
            const float w1 = qw1[lq];
#pragma unroll
            for (int ct = 0; ct < 4; ct++) {
                const int t = qt * 4 + ct;
                const int lc = cw + ct * 8 + 2 * tig;
#pragma unroll
                for (int m = 0; m < 2; m++) {
                    const float dh = acc[t][half * 2 + m];
                    const float yn = cyn[lc + m];
                    float s1 = fmaf(-2.f, dh, 1.f);
                    float alpha = s1 + yn;
                    float num = fmaf(alpha, fmaf(alpha, xn, nb * dh), bb * yn);
                    float den = fmaxf(fmaf(xn, yn, s1), 1e-15f);
                    float tv = f_sqrt(fmaxf(num, 0.f)) * f_rcp(den);
                    tv = fminf(tv, 0.99999994f);
                    float L = f_lg2((1.f + tv) * f_rcp(1.f - tv));
                    tot[t][half * 2 + m] = fmaf(w1, L * L, tot[t][half * 2 + m]);
                }
            }
        }
    }

    // ================= phase s =================
#pragma unroll
    for (int t = 0; t < 8; t++)
#pragma unroll
        for (int m = 0; m < 4; m++) acc[t][m] = 0.f;
    __syncthreads();
    stage(48);
    __syncthreads();
    seg_mma(acc);
#pragma unroll
    for (int qt = 0; qt < 2; qt++) {
        const int lqA = qw + qt * 16 + gid;
#pragma unroll
        for (int half = 0; half < 2; half++) {
            const int lq = lqA + half * 8;
            const float w2 = qw2[lq];
#pragma unroll
            for (int ct = 0; ct < 4; ct++) {
                const int t = qt * 4 + ct;
#pragma unroll
                for (int m = 0; m < 2; m++) {
                    const float d = acc[t][half * 2 + m];
                    float ad = fminf(fabsf(d), 1.f);
                    float sq = f_sqrt(fmaxf(1.f - ad, 0.f));
                    float p = -0.0012624911f;
                    p = fmaf(p, ad,  0.0066700901f);
                    p = fmaf(p, ad, -0.0170881256f);
                    p = fmaf(p, ad,  0.0308918810f);
                    p = fmaf(p, ad, -0.0501743046f);
                    p = fmaf(p, ad,  0.0889789874f);
                    p = fmaf(p, ad, -0.2145988016f);
                    p = fmaf(p, ad,  1.5707963050f);
                    float r = sq * p;
                    float a = (d >= 0.f) ? r : 3.14159265358979f - r;
                    tot[t][half * 2 + m] = fmaf(w2, a * a, tot[t][half * 2 + m]);
                }
            }
        }
    }

    // ================= store -total =================
#pragma unroll
    for (int qt = 0; qt < 2; qt++) {
        const int lqA = qw + qt * 16 + gid;
#pragma unroll
        for (int ct = 0; ct < 4; ct++) {
            const int t = qt * 4 + ct;
            const int lc = cw + ct * 8 + 2 * tig;
            float2 oA = make_float2(-tot[t][0], -tot[t][1]);
            float2 oB = make_float2(-tot[t][2], -tot[t][3]);
            *(float2*)(out + (size_t)(q0 + lqA) * NC + c0 + lc)     = oA;
            *(float2*)(out + (size_t)(q0 + lqA + 8) * NC + c0 + lc) = oB;
        }
    }
}

// ---------------------------------------------------------------------------
extern "C" void kernel_launch(void* const* d_in, const int* in_sizes, int n_in,
                              void* d_out, int out_size)
{
    const float* x_q  = (const float*)d_in[0];
    const float* x_c  = (const float*)d_in[1];
    const float* We   = (const float*)d_in[2];
    const float* be   = (const float*)d_in[3];
    const float* Wh   = (const float*)d_in[4];
    const float* bh   = (const float*)d_in[5];
    const float* Ws   = (const float*)d_in[6];
    const float* bs   = (const float*)d_in[7];
    const float* scl  = (const float*)d_in[8];
    const float* W1   = (const float*)d_in[9];
    const float* b1   = (const float*)d_in[10];
    const float* W2   = (const float*)d_in[11];
    const float* b2   = (const float*)d_in[12];
    float* out = (float*)d_out;

    float *cfT, *cfLo, *qfT, *qfLo, *wHi, *wLo, *part;
    cudaGetSymbolAddress((void**)&cfT,  g_cfeatT);
    cudaGetSymbolAddress((void**)&cfLo, g_cfeatLo);
    cudaGetSymbolAddress((void**)&qfT,  g_qfeatT);
    cudaGetSymbolAddress((void**)&qfLo, g_qfeatLo);
    cudaGetSymbolAddress((void**)&wHi,  g_wHi);
    cudaGetSymbolAddress((void**)&wLo,  g_wLo);
    cudaGetSymbolAddress((void**)&part, g_part);

    wsplit_kernel<<<(64 * DIN + 255) / 256, 256>>>(We, Wh, Ws, wHi, wLo);
    projmma_kernel<<<NC / 64, 128>>>(x_c, be, bh, bs, scl, wHi, wLo, cfT, cfLo, NC, 0);
    projmma_kernel<<<NQ / 64, 128>>>(x_q, be, bh, bs, scl, wHi, wLo, qfT, qfLo, NQ, 1);
    mlpq_part_kernel<<<dim3(NQ / 64, 6), 256>>>(x_q, W1, part);
    mlpq_fin_kernel<<<NQ / 256, 256>>>(part, b1, W2, b2, qfT);
    pair_kernel<<<dim3(NC / 128, NQ / 64), 256>>>(qfT, qfLo, cfT, cfLo, out);
}

// round 12
// speedup vs baseline: 1.6458x; 1.0948x over previous
#include <cuda_runtime.h>
#include <math.h>

#define NQ 512
#define NC 65536
#define DIN 768

// Scratch (static device globals).
__device__ float g_cfeatT[65 * NC];    // corpus: rows 0..63 hi, 64 = yn
__device__ float g_cfeatLo[64 * NC];
__device__ float g_qfeatT[69 * NQ];    // query: 0..63 hi, 64 xn, 65 beta, 66 w0, 67 w1*ln2^2, 68 w2
__device__ float g_qfeatLo[64 * NQ];
__device__ float g_wHi[64 * DIN];      // concatenated We/Wh/Ws tf32 hi
__device__ float g_wLo[64 * DIN];      // ... lo residual
__device__ float g_part[6 * NQ * 32];  // mlp split-K partials

// ---------------- helpers ----------------
__device__ __forceinline__ float f_rcp(float x)  { float r; asm("rcp.approx.f32 %0,%1;"  : "=f"(r) : "f"(x)); return r; }
__device__ __forceinline__ float f_sqrt(float x) { float r; asm("sqrt.approx.f32 %0,%1;" : "=f"(r) : "f"(x)); return r; }
__device__ __forceinline__ float f_lg2(float x)  { float r; asm("lg2.approx.f32 %0,%1;"  : "=f"(r) : "f"(x)); return r; }
__device__ __forceinline__ float tf32_rna(float x) {
    unsigned u; asm("cvt.rna.tf32.f32 %0,%1;" : "=r"(u) : "f"(x)); return __uint_as_float(u);
}
__device__ __forceinline__ void mma_tf32(float c[4], const unsigned a[4], const unsigned b[2]) {
    asm volatile(
        "mma.sync.aligned.m16n8k8.row.col.f32.tf32.tf32.f32 "
        "{%0,%1,%2,%3},{%4,%5,%6,%7},{%8,%9},{%0,%1,%2,%3};"
        : "+f"(c[0]), "+f"(c[1]), "+f"(c[2]), "+f"(c[3])
        : "r"(a[0]), "r"(a[1]), "r"(a[2]), "r"(a[3]), "r"(b[0]), "r"(b[1]));
}

// ---------------------------------------------------------------------------
// One-time W split: concatenated [64][768] tf32 hi/lo planes
// ---------------------------------------------------------------------------
__global__ void wsplit_kernel(const float* __restrict__ We,
                              const float* __restrict__ Wh,
                              const float* __restrict__ Ws,
                              float* __restrict__ wHi, float* __restrict__ wLo)
{
    int i = blockIdx.x * 256 + threadIdx.x;
    if (i >= 64 * DIN) return;
    int d = i / DIN;
    int k = i - d * DIN;
    float v = (d < 32) ? We[d * DIN + k]
            : (d < 48) ? Wh[(d - 32) * DIN + k]
                       : Ws[(d - 48) * DIN + k];
    float hi = tf32_rna(v);
    wHi[i] = hi;
    wLo[i] = tf32_rna(v - hi);
}

// ---------------------------------------------------------------------------
// Projection (tf32 MMA v4): 64 rows x 64 dims per CTA, 128 threads (4 warps),
// 2x2 warp layout (32 rows x 32 dims per warp: balanced fragment traffic),
// ping-pong double-buffered staging (one sync per k-chunk), 4 CTAs/SM.
// ---------------------------------------------------------------------------
#define PBUF 4608   // floats per staging buffer: 4 arrays x 16 x 72

__global__ __launch_bounds__(128, 4) void projmma_kernel(
    const float* __restrict__ X,
    const float* __restrict__ be, const float* __restrict__ bh,
    const float* __restrict__ bs, const float* __restrict__ scale_p,
    const float* __restrict__ wHi, const float* __restrict__ wLo,
    float* __restrict__ featT, float* __restrict__ featLo,
    int fstride, int is_query)
{
    __shared__ __align__(16) float sbuf[2 * PBUF];       // 36.9 KB
    float (*psm)[69] = (float(*)[69])(sbuf);             // 64 x 69 (aliases buf0)

    const int tid  = threadIdx.x;
    const int lane = tid & 31;
    const int warp = tid >> 5;
    const int gid  = lane >> 2;
    const int tig  = lane & 3;
    const int mrow = (warp & 1) * 32;    // row-group origin
    const int ncol = (warp >> 1) * 32;   // dim-group origin
    const int row0 = blockIdx.x * 64;

    const int rA = tid >> 1;         // 0..63 (x-row / w-dim)
    const int k8 = (tid & 1) * 8;    // 0 or 8

    const float* Xp  = X   + (size_t)(row0 + rA) * DIN + k8;
    const float* WHp = wHi + rA * DIN + k8;
    const float* WLp = wLo + rA * DIN + k8;

    float4 xv0 = *(const float4*)(Xp);
    float4 xv1 = *(const float4*)(Xp + 4);
    float4 wh0 = *(const float4*)(WHp);
    float4 wh1 = *(const float4*)(WHp + 4);
    float4 wl0 = *(const float4*)(WLp);
    float4 wl1 = *(const float4*)(WLp + 4);

    float acc[2][4][4];
#pragma unroll
    for (int mt = 0; mt < 2; mt++)
#pragma unroll
        for (int ct = 0; ct < 4; ct++)
#pragma unroll
            for (int m = 0; m < 4; m++) acc[mt][ct][m] = 0.f;

    // store current prefetch regs into staging buffer p
    auto store_stage = [&](int p) {
        float* xshp = sbuf + p * PBUF;
        float* xslp = xshp + 1152;
        float* wshp = xshp + 2304;
        float* wslp = xshp + 3456;
        const float* p0 = (const float*)&xv0;
        const float* p1 = (const float*)&xv1;
        const float* h0 = (const float*)&wh0;
        const float* h1 = (const float*)&wh1;
        const float* l0 = (const float*)&wl0;
        const float* l1 = (const float*)&wl1;
#pragma unroll
        for (int u = 0; u < 4; u++) {
            float a0 = tf32_rna(p0[u]);
            float a1 = tf32_rna(p1[u]);
            xshp[(k8 + u) * 72 + rA]     = a0;
            xslp[(k8 + u) * 72 + rA]     = tf32_rna(p0[u] - a0);
            xshp[(k8 + 4 + u) * 72 + rA] = a1;
            xslp[(k8 + 4 + u) * 72 + rA] = tf32_rna(p1[u] - a1);
            wshp[(k8 + u) * 72 + rA]     = h0[u];
            wshp[(k8 + 4 + u) * 72 + rA] = h1[u];
            wslp[(k8 + u) * 72 + rA]     = l0[u];
            wslp[(k8 + 4 + u) * 72 + rA] = l1[u];
        }
    };

    store_stage(0);
    __syncthreads();

    for (int i = 0; i < 48; i++) {
        const int k0n = (i + 1) * 16;
        if (i + 1 < 48) {
            xv0 = *(const float4*)(Xp  + k0n);
            xv1 = *(const float4*)(Xp  + k0n + 4);
            wh0 = *(const float4*)(WHp + k0n);
            wh1 = *(const float4*)(WHp + k0n + 4);
            wl0 = *(const float4*)(WLp + k0n);
            wl1 = *(const float4*)(WLp + k0n + 4);
        }
        {
            const float* xshp = sbuf + (i & 1) * PBUF;
            const float* xslp = xshp + 1152;
            const float* wshp = xshp + 2304;
            const float* wslp = xshp + 3456;
#pragma unroll
            for (int kc = 0; kc < 2; kc++) {
                const int ks = kc * 8;
                unsigned ah[2][4], al[2][4];
#pragma unroll
                for (int mt = 0; mt < 2; mt++) {
                    const int r = mrow + mt * 16 + gid;
                    ah[mt][0] = __float_as_uint(xshp[(ks + tig) * 72 + r]);
                    ah[mt][1] = __float_as_uint(xshp[(ks + tig) * 72 + r + 8]);
                    ah[mt][2] = __float_as_uint(xshp[(ks + tig + 4) * 72 + r]);
                    ah[mt][3] = __float_as_uint(xshp[(ks + tig + 4) * 72 + r + 8]);
                    al[mt][0] = __float_as_uint(xslp[(ks + tig) * 72 + r]);
                    al[mt][1] = __float_as_uint(xslp[(ks + tig) * 72 + r + 8]);
                    al[mt][2] = __float_as_uint(xslp[(ks + tig + 4) * 72 + r]);
                    al[mt][3] = __float_as_uint(xslp[(ks + tig + 4) * 72 + r + 8]);
                }
#pragma unroll
                for (int ct = 0; ct < 4; ct++) {
                    const int cc = ncol + ct * 8 + gid;
                    unsigned bh2[2], bl2[2];
                    bh2[0] = __float_as_uint(wshp[(ks + tig) * 72 + cc]);
                    bh2[1] = __float_as_uint(wshp[(ks + tig + 4) * 72 + cc]);
                    bl2[0] = __float_as_uint(wslp[(ks + tig) * 72 + cc]);
                    bl2[1] = __float_as_uint(wslp[(ks + tig + 4) * 72 + cc]);
#pragma unroll
                    for (int mt = 0; mt < 2; mt++) {
                        mma_tf32(acc[mt][ct], ah[mt], bh2);
                        mma_tf32(acc[mt][ct], ah[mt], bl2);
                        mma_tf32(acc[mt][ct], al[mt], bh2);
                    }
                }
            }
        }
        if (i + 1 < 48) store_stage((i + 1) & 1);
        __syncthreads();
    }

    // epilogue: bias into psm (aliases buf0; last MMA read buf1 or is synced)
    {
#pragma unroll
        for (int mt = 0; mt < 2; mt++) {
            const int r = mrow + mt * 16 + gid;
#pragma unroll
            for (int ct = 0; ct < 4; ct++) {
#pragma unroll
                for (int u = 0; u < 2; u++) {
                    const int d = ncol + ct * 8 + 2 * tig + u;
                    float bias = (d < 32) ? __ldg(be + d)
                               : (d < 48) ? __ldg(bh + d - 32)
                                          : __ldg(bs + d - 48);
                    psm[r][d]     = acc[mt][ct][u]     + bias;
                    psm[r + 8][d] = acc[mt][ct][2 + u] + bias;
                }
            }
        }
    }
    __syncthreads();

    if (tid < 64) {
        const int r = tid;
        const float sc = *scale_p;
        float s2 = 0.f;
#pragma unroll
        for (int k = 0; k < 32; k++) { float v = psm[r][k]; s2 = fmaf(v, v, s2); }
        float inv = 1.0f / sqrtf(s2);
#pragma unroll
        for (int k = 0; k < 32; k++) psm[r][k] *= inv;
        float h2 = 0.f;
#pragma unroll
        for (int k = 32; k < 48; k++) { float v = psm[r][k] * sc; psm[r][k] = v; h2 = fmaf(v, v, h2); }
        float n  = fmaxf(sqrtf(h2), 1e-15f);
        float th = tanhf(n);
        float fac = th / n;
#pragma unroll
        for (int k = 32; k < 48; k++) psm[r][k] *= fac;
        psm[r][64] = th * th;                       // yn / xn
        if (is_query) psm[r][65] = 1.0f - th * th;  // beta
        float s3 = 0.f;
#pragma unroll
        for (int k = 48; k < 64; k++) { float v = psm[r][k]; s3 = fmaf(v, v, s3); }
        float inv3 = 1.0f / sqrtf(s3);
#pragma unroll
        for (int k = 48; k < 64; k++) psm[r][k] *= inv3;
    }
    __syncthreads();

    // features: hi/lo split, coalesced (64-wide rows)
    for (int i = tid; i < 64 * 64; i += 128) {
        int k = i >> 6, r = i & 63;
        float v = psm[r][k];
        float hi = tf32_rna(v);
        float lo = tf32_rna(v - hi);
        featT [(size_t)k * fstride + row0 + r] = hi;
        featLo[(size_t)k * fstride + row0 + r] = lo;
    }
    const int np = is_query ? 2 : 1;
    for (int i = tid; i < np * 64; i += 128) {
        int k = 64 + (i >> 6), r = i & 63;
        featT[(size_t)k * fstride + row0 + r] = psm[r][k];
    }
}

// ---------------------------------------------------------------------------
// Weight-MLP layer 1, split-K with register prefetch: partials -> g_part
// grid = (8 row-blocks, 6 K-chunks), 256 threads
// ---------------------------------------------------------------------------
__global__ __launch_bounds__(256) void mlpq_part_kernel(
    const float* __restrict__ X, const float* __restrict__ W1,
    float* __restrict__ part)
{
    __shared__ __align__(16) float xs[16][68];
    __shared__ __align__(16) float ws[16][36];
    const int tid = threadIdx.x;
    const int r0 = (tid >> 3) * 2;
    const int d0 = (tid & 7) * 4;
    const int row0 = blockIdx.x * 64;
    const int kc   = blockIdx.y;            // 0..5
    const int kbeg = kc * 128;
    const int lr = tid >> 2;
    const int lk = (tid & 3) * 4;

    const float* Xp = X + (size_t)(row0 + lr) * DIN + kbeg + lk;
    const float* Wp = W1 + lr * DIN + kbeg + lk;

    float4 xv = *(const float4*)(Xp);
    float4 wv = make_float4(0.f, 0.f, 0.f, 0.f);
    if (tid < 128) wv = *(const float4*)(Wp);

    float acc[2][4] = {};
    for (int kk0 = 0; kk0 < 128; kk0 += 16) {
        __syncthreads();
        xs[lk + 0][lr] = xv.x; xs[lk + 1][lr] = xv.y;
        xs[lk + 2][lr] = xv.z; xs[lk + 3][lr] = xv.w;
        if (tid < 128) {
            ws[lk + 0][lr] = wv.x; ws[lk + 1][lr] = wv.y;
            ws[lk + 2][lr] = wv.z; ws[lk + 3][lr] = wv.w;
        }
        __syncthreads();
        if (kk0 + 16 < 128) {
            xv = *(const float4*)(Xp + kk0 + 16);
            if (tid < 128) wv = *(const float4*)(Wp + kk0 + 16);
        }
#pragma unroll
        for (int kk = 0; kk < 16; kk++) {
            float a0 = xs[kk][r0];
            float a1 = xs[kk][r0 + 1];
            float4 b4 = *(const float4*)&ws[kk][d0];
            float bv[4] = {b4.x, b4.y, b4.z, b4.w};
#pragma unroll
            for (int j = 0; j < 4; j++) {
                acc[0][j] = fmaf(a0, bv[j], acc[0][j]);
                acc[1][j] = fmaf(a1, bv[j], acc[1][j]);
            }
        }
    }
    float* dst = part + (size_t)kc * NQ * 32;
#pragma unroll
    for (int i = 0; i < 2; i++)
#pragma unroll
        for (int j = 0; j < 4; j++)
            dst[(size_t)(row0 + r0 + i) * 32 + d0 + j] = acc[i][j];
}

// ---------------------------------------------------------------------------
// Weight-MLP finish: sum partials + b1, relu, layer2 + softplus -> qfT 66..68
// ---------------------------------------------------------------------------
__global__ __launch_bounds__(256) void mlpq_fin_kernel(
    const float* __restrict__ part, const float* __restrict__ b1,
    const float* __restrict__ W2, const float* __restrict__ b2,
    float* __restrict__ qfT)
{
    const int q = blockIdx.x * 256 + threadIdx.x;
    if (q >= NQ) return;
    float y[32];
#pragma unroll
    for (int d = 0; d < 32; d += 4) {
        float4 s = *(const float4*)(part + (size_t)q * 32 + d);
#pragma unroll
        for (int kc = 1; kc < 6; kc++) {
            float4 p = *(const float4*)(part + (size_t)kc * NQ * 32 + (size_t)q * 32 + d);
            s.x += p.x; s.y += p.y; s.z += p.z; s.w += p.w;
        }
        y[d]     = fmaxf(s.x + __ldg(b1 + d),     0.f);
        y[d + 1] = fmaxf(s.y + __ldg(b1 + d + 1), 0.f);
        y[d + 2] = fmaxf(s.z + __ldg(b1 + d + 2), 0.f);
        y[d + 3] = fmaxf(s.w + __ldg(b1 + d + 3), 0.f);
    }
    float z0 = b2[0], z1 = b2[1], z2 = b2[2];
#pragma unroll
    for (int k = 0; k < 32; k++) {
        z0 = fmaf(y[k], __ldg(W2 + k),      z0);
        z1 = fmaf(y[k], __ldg(W2 + 32 + k), z1);
        z2 = fmaf(y[k], __ldg(W2 + 64 + k), z2);
    }
    float sp0 = fmaxf(z0, 0.f) + log1pf(expf(-fabsf(z0)));
    float sp1 = fmaxf(z1, 0.f) + log1pf(expf(-fabsf(z1)));
    float sp2 = fmaxf(z2, 0.f) + log1pf(expf(-fabsf(z2)));
    qfT[(size_t)66 * NQ + q] = sp0;
    qfT[(size_t)67 * NQ + q] = sp1 * 0.4804530139182014f;  // fold ln2^2
    qfT[(size_t)68 * NQ + q] = sp2;
}

// ---------------------------------------------------------------------------
// Pairwise kernel: 64q x 128c per CTA, 8 warps of 32x32, tf32 MMA split hi/lo
// Early-LDG prefetch: next phase's gmem loads issue before current MMA.
// ---------------------------------------------------------------------------
__global__ __launch_bounds__(256, 2) void pair_kernel(
    const float* __restrict__ qfT, const float* __restrict__ qfLo,
    const float* __restrict__ cfT, const float* __restrict__ cfLo,
    float* __restrict__ out)
{
    __shared__ __align__(16) float sqh[16][72], sql[16][72];
    __shared__ __align__(16) float sch[16][136], sclo[16][136];
    __shared__ float qxn[64], qbt[64], qw0[64], qw1[64], qw2[64], cyn[128];

    const int tid  = threadIdx.x;
    const int lane = tid & 31;
    const int warp = tid >> 5;
    const int gid  = lane >> 2;
    const int tig  = lane & 3;
    const int qw   = (warp >> 2) * 32;
    const int cw   = (warp & 3) * 32;

    const int q0 = blockIdx.y * 64;
    const int c0 = blockIdx.x * 128;

    // staging index precompute
    const int qrow = tid >> 4;            // 0..15
    const int qc4  = (tid & 15) * 4;      // 0..60
    const int crow = tid >> 5;            // 0..7  (second half = +8)
    const int cc4  = (tid & 31) * 4;      // 0..124

    float4 pqh, pql, pch0, pcl0, pch1, pcl1;
    auto ld_stage = [&](int off) {
        pqh  = *(const float4*)(qfT  + (size_t)(off + qrow) * NQ + q0 + qc4);
        pql  = *(const float4*)(qfLo + (size_t)(off + qrow) * NQ + q0 + qc4);
        pch0 = *(const float4*)(cfT  + (size_t)(off + crow) * NC + c0 + cc4);
        pcl0 = *(const float4*)(cfLo + (size_t)(off + crow) * NC + c0 + cc4);
        pch1 = *(const float4*)(cfT  + (size_t)(off + crow + 8) * NC + c0 + cc4);
        pcl1 = *(const float4*)(cfLo + (size_t)(off + crow + 8) * NC + c0 + cc4);
    };
    auto st_stage = [&]() {
        *(float4*)&sqh[qrow][qc4]      = pqh;
        *(float4*)&sql[qrow][qc4]      = pql;
        *(float4*)&sch[crow][cc4]      = pch0;
        *(float4*)&sclo[crow][cc4]     = pcl0;
        *(float4*)&sch[crow + 8][cc4]  = pch1;
        *(float4*)&sclo[crow + 8][cc4] = pcl1;
    };

    ld_stage(0);

    if (tid < 64) {
        qxn[tid] = qfT[(size_t)64 * NQ + q0 + tid];
        qbt[tid] = qfT[(size_t)65 * NQ + q0 + tid];
        qw0[tid] = qfT[(size_t)66 * NQ + q0 + tid];
        qw1[tid] = qfT[(size_t)67 * NQ + q0 + tid];
        qw2[tid] = qfT[(size_t)68 * NQ + q0 + tid];
    } else if (tid < 192) {
        const int r = tid - 64;
        cyn[r] = cfT[(size_t)64 * NC + c0 + r];
    }

    auto seg_mma = [&](float acc[8][4]) {
#pragma unroll
        for (int kc = 0; kc < 2; kc++) {
            const int k0 = kc * 8;
            unsigned bh[4][2], bl[4][2];
#pragma unroll
            for (int ct = 0; ct < 4; ct++) {
                const int cc = cw + ct * 8 + gid;
                bh[ct][0] = __float_as_uint(sch [k0 + tig][cc]);
                bh[ct][1] = __float_as_uint(sch [k0 + tig + 4][cc]);
                bl[ct][0] = __float_as_uint(sclo[k0 + tig][cc]);
                bl[ct][1] = __float_as_uint(sclo[k0 + tig + 4][cc]);
            }
#pragma unroll
            for (int qt = 0; qt < 2; qt++) {
                const int r = qw + qt * 16 + gid;
                unsigned ah[4], al[4];
                ah[0] = __float_as_uint(sqh[k0 + tig][r]);
                ah[1] = __float_as_uint(sqh[k0 + tig][r + 8]);
                ah[2] = __float_as_uint(sqh[k0 + tig + 4][r]);
                ah[3] = __float_as_uint(sqh[k0 + tig + 4][r + 8]);
                al[0] = __float_as_uint(sql[k0 + tig][r]);
                al[1] = __float_as_uint(sql[k0 + tig][r + 8]);
                al[2] = __float_as_uint(sql[k0 + tig + 4][r]);
                al[3] = __float_as_uint(sql[k0 + tig + 4][r + 8]);
#pragma unroll
                for (int ct = 0; ct < 4; ct++) {
                    float* a = acc[qt * 4 + ct];
                    mma_tf32(a, ah, bh[ct]);
                    mma_tf32(a, ah, bl[ct]);
                    mma_tf32(a, al, bh[ct]);
                }
            }
        }
    };

    float tot[8][4];
    float acc[8][4];

    // ================= phase e (rows 0..31: two segments) =================
#pragma unroll
    for (int t = 0; t < 8; t++)
#pragma unroll
        for (int m = 0; m < 4; m++) acc[t][m] = 0.f;
    st_stage();
    __syncthreads();
    ld_stage(16);                 // prefetch segment 2 (hidden under mma)
    seg_mma(acc);
    __syncthreads();
    st_stage();
    __syncthreads();
    ld_stage(32);                 // prefetch phase h
    seg_mma(acc);
#pragma unroll
    for (int qt = 0; qt < 2; qt++) {
        const int lqA = qw + qt * 16 + gid;
        const float wA = qw0[lqA], wB = qw0[lqA + 8];
#pragma unroll
        for (int ct = 0; ct < 4; ct++) {
            const int t = qt * 4 + ct;
            tot[t][0] = wA * (2.f - 2.f * acc[t][0]);
            tot[t][1] = wA * (2.f - 2.f * acc[t][1]);
            tot[t][2] = wB * (2.f - 2.f * acc[t][2]);
            tot[t][3] = wB * (2.f - 2.f * acc[t][3]);
        }
    }

    // ================= phase h =================
#pragma unroll
    for (int t = 0; t < 8; t++)
#pragma unroll
        for (int m = 0; m < 4; m++) acc[t][m] = 0.f;
    __syncthreads();
    st_stage();
    __syncthreads();
    ld_stage(48);                 // prefetch phase s
    seg_mma(acc);
#pragma unroll
    for (int qt = 0; qt < 2; qt++) {
        const int lqA = qw + qt * 16 + gid;
#pragma unroll
        for (int half = 0; half < 2; half++) {
            const int lq = lqA + half * 8;
            const float xn = qxn[lq];
            const float bt = qbt[lq];
            const float nb = -2.f * bt;
            const float bb = bt * bt;
            const float w1 = qw1[lq];
#pragma unroll
            for (int ct = 0; ct < 4; ct++) {
                const int t = qt * 4 + ct;
                const int lc = cw + ct * 8 + 2 * tig;
#pragma unroll
                for (int m = 0; m < 2; m++) {
                    const float dh = acc[t][half * 2 + m];
                    const float yn = cyn[lc + m];
                    float s1 = fmaf(-2.f, dh, 1.f);
                    float alpha = s1 + yn;
                    float num = fmaf(alpha, fmaf(alpha, xn, nb * dh), bb * yn);
                    float den = fmaxf(fmaf(xn, yn, s1), 1e-15f);
                    float tv = f_sqrt(fmaxf(num, 0.f)) * f_rcp(den);
                    tv = fminf(tv, 0.99999994f);
                    float L = f_lg2((1.f + tv) * f_rcp(1.f - tv));
                    tot[t][half * 2 + m] = fmaf(w1, L * L, tot[t][half * 2 + m]);
                }
            }
        }
    }

    // ================= phase s =================
#pragma unroll
    for (int t = 0; t < 8; t++)
#pragma unroll
        for (int m = 0; m < 4; m++) acc[t][m] = 0.f;
    __syncthreads();
    st_stage();
    __syncthreads();
    seg_mma(acc);
#pragma unroll
    for (int qt = 0; qt < 2; qt++) {
        const int lqA = qw + qt * 16 + gid;
#pragma unroll
        for (int half = 0; half < 2; half++) {
            const int lq = lqA + half * 8;
            const float w2 = qw2[lq];
#pragma unroll
            for (int ct = 0; ct < 4; ct++) {
                const int t = qt * 4 + ct;
#pragma unroll
                for (int m = 0; m < 2; m++) {
                    const float d = acc[t][half * 2 + m];
                    float ad = fminf(fabsf(d), 1.f);
                    float sq = f_sqrt(fmaxf(1.f - ad, 0.f));
                    float p = -0.0012624911f;
                    p = fmaf(p, ad,  0.0066700901f);
                    p = fmaf(p, ad, -0.0170881256f);
                    p = fmaf(p, ad,  0.0308918810f);
                    p = fmaf(p, ad, -0.0501743046f);
                    p = fmaf(p, ad,  0.0889789874f);
                    p = fmaf(p, ad, -0.2145988016f);
                    p = fmaf(p, ad,  1.5707963050f);
                    float r = sq * p;
                    float a = (d >= 0.f) ? r : 3.14159265358979f - r;
                    tot[t][half * 2 + m] = fmaf(w2, a * a, tot[t][half * 2 + m]);
                }
            }
        }
    }

    // ================= store -total =================
#pragma unroll
    for (int qt = 0; qt < 2; qt++) {
        const int lqA = qw + qt * 16 + gid;
#pragma unroll
        for (int ct = 0; ct < 4; ct++) {
            const int t = qt * 4 + ct;
            const int lc = cw + ct * 8 + 2 * tig;
            float2 oA = make_float2(-tot[t][0], -tot[t][1]);
            float2 oB = make_float2(-tot[t][2], -tot[t][3]);
            *(float2*)(out + (size_t)(q0 + lqA) * NC + c0 + lc)     = oA;
            *(float2*)(out + (size_t)(q0 + lqA + 8) * NC + c0 + lc) = oB;
        }
    }
}

// ---------------------------------------------------------------------------
extern "C" void kernel_launch(void* const* d_in, const int* in_sizes, int n_in,
                              void* d_out, int out_size)
{
    const float* x_q  = (const float*)d_in[0];
    const float* x_c  = (const float*)d_in[1];
    const float* We   = (const float*)d_in[2];
    const float* be   = (const float*)d_in[3];
    const float* Wh   = (const float*)d_in[4];
    const float* bh   = (const float*)d_in[5];
    const float* Ws   = (const float*)d_in[6];
    const float* bs   = (const float*)d_in[7];
    const float* scl  = (const float*)d_in[8];
    const float* W1   = (const float*)d_in[9];
    const float* b1   = (const float*)d_in[10];
    const float* W2   = (const float*)d_in[11];
    const float* b2   = (const float*)d_in[12];
    float* out = (float*)d_out;

    float *cfT, *cfLo, *qfT, *qfLo, *wHi, *wLo, *part;
    cudaGetSymbolAddress((void**)&cfT,  g_cfeatT);
    cudaGetSymbolAddress((void**)&cfLo, g_cfeatLo);
    cudaGetSymbolAddress((void**)&qfT,  g_qfeatT);
    cudaGetSymbolAddress((void**)&qfLo, g_qfeatLo);
    cudaGetSymbolAddress((void**)&wHi,  g_wHi);
    cudaGetSymbolAddress((void**)&wLo,  g_wLo);
    cudaGetSymbolAddress((void**)&part, g_part);

    wsplit_kernel<<<(64 * DIN + 255) / 256, 256>>>(We, Wh, Ws, wHi, wLo);
    projmma_kernel<<<NC / 64, 128>>>(x_c, be, bh, bs, scl, wHi, wLo, cfT, cfLo, NC, 0);
    projmma_kernel<<<NQ / 64, 128>>>(x_q, be, bh, bs, scl, wHi, wLo, qfT, qfLo, NQ, 1);
    mlpq_part_kernel<<<dim3(NQ / 64, 6), 256>>>(x_q, W1, part);
    mlpq_fin_kernel<<<NQ / 256, 256>>>(part, b1, W2, b2, qfT);
    pair_kernel<<<dim3(NC / 128, NQ / 64), 256>>>(qfT, qfLo, cfT, cfLo, out);
}

// round 14
// speedup vs baseline: 1.8729x; 1.1380x over previous
#include <cuda_runtime.h>
#include <math.h>

#define NQ 512
#define NC 65536
#define DIN 768

// Scratch (static device globals).
__device__ float g_cfeatT[65 * NC];    // corpus: rows 0..63 hi, 64 = yn
__device__ float g_cfeatLo[64 * NC];
__device__ float g_qfeatT[69 * NQ];    // query: 0..63 hi, 64 xn, 65 beta, 66 w0, 67 w1*ln2^2, 68 w2
__device__ float g_qfeatLo[64 * NQ];
__device__ float g_wHi[64 * DIN];      // concatenated We/Wh/Ws tf32 hi
__device__ float g_wLo[64 * DIN];      // ... lo residual
__device__ float g_part[6 * NQ * 32];  // mlp split-K partials

// ---------------- helpers ----------------
__device__ __forceinline__ float f_rcp(float x)  { float r; asm("rcp.approx.f32 %0,%1;"  : "=f"(r) : "f"(x)); return r; }
__device__ __forceinline__ float f_sqrt(float x) { float r; asm("sqrt.approx.f32 %0,%1;" : "=f"(r) : "f"(x)); return r; }
__device__ __forceinline__ float f_lg2(float x)  { float r; asm("lg2.approx.f32 %0,%1;"  : "=f"(r) : "f"(x)); return r; }
__device__ __forceinline__ float tf32_rna(float x) {
    unsigned u; asm("cvt.rna.tf32.f32 %0,%1;" : "=r"(u) : "f"(x)); return __uint_as_float(u);
}
__device__ __forceinline__ void mma_tf32(float c[4], const unsigned a[4], const unsigned b[2]) {
    asm volatile(
        "mma.sync.aligned.m16n8k8.row.col.f32.tf32.tf32.f32 "
        "{%0,%1,%2,%3},{%4,%5,%6,%7},{%8,%9},{%0,%1,%2,%3};"
        : "+f"(c[0]), "+f"(c[1]), "+f"(c[2]), "+f"(c[3])
        : "r"(a[0]), "r"(a[1]), "r"(a[2]), "r"(a[3]), "r"(b[0]), "r"(b[1]));
}
__device__ __forceinline__ void cp_async16(unsigned dst, const void* src) {
    asm volatile("cp.async.cg.shared.global [%0], [%1], 16;" :: "r"(dst), "l"(src) : "memory");
}
#define CP_COMMIT() asm volatile("cp.async.commit_group;" ::: "memory")
#define CP_WAIT0()  asm volatile("cp.async.wait_group 0;" ::: "memory")

// ---------------------------------------------------------------------------
// One-time W split: concatenated [64][768] tf32 hi/lo planes
// ---------------------------------------------------------------------------
__global__ void wsplit_kernel(const float* __restrict__ We,
                              const float* __restrict__ Wh,
                              const float* __restrict__ Ws,
                              float* __restrict__ wHi, float* __restrict__ wLo)
{
    int i = blockIdx.x * 256 + threadIdx.x;
    if (i >= 64 * DIN) return;
    int d = i / DIN;
    int k = i - d * DIN;
    float v = (d < 32) ? We[d * DIN + k]
            : (d < 48) ? Wh[(d - 32) * DIN + k]
                       : Ws[(d - 48) * DIN + k];
    float hi = tf32_rna(v);
    wHi[i] = hi;
    wLo[i] = tf32_rna(v - hi);
}

// ---------------------------------------------------------------------------
// Projection (tf32 MMA v5): 64 rows x 64 dims per CTA, 128 threads (4 warps),
// 2x2 warp layout, ping-pong staging with ONE sync per chunk.
// W staged via cp.async (dim-major [64][20] pad, conflict-free), 5 CTAs/SM.
// Buffer layout (floats): xsh 0..1151 [16][72], xsl 1152.., wsh 2304 [64][20],
// wsl 3584..; PBUF=4864.
// ---------------------------------------------------------------------------
#define PBUF 4864

__global__ __launch_bounds__(128, 5) void projmma_kernel(
    const float* __restrict__ X,
    const float* __restrict__ be, const float* __restrict__ bh,
    const float* __restrict__ bs, const float* __restrict__ scale_p,
    const float* __restrict__ wHi, const float* __restrict__ wLo,
    float* __restrict__ featT, float* __restrict__ featLo,
    int fstride, int is_query)
{
    __shared__ __align__(16) float sbuf[2 * PBUF];       // 38.9 KB
    float (*psm)[69] = (float(*)[69])(sbuf);             // 64 x 69 (aliases buf0)

    const int tid  = threadIdx.x;
    const int lane = tid & 31;
    const int warp = tid >> 5;
    const int gid  = lane >> 2;
    const int tig  = lane & 3;
    const int mrow = (warp & 1) * 32;
    const int ncol = (warp >> 1) * 32;
    const int row0 = blockIdx.x * 64;

    const int rA = tid >> 1;         // 0..63 (x-row / w-dim)
    const int k8 = (tid & 1) * 8;    // 0 or 8

    const float* Xp  = X + (size_t)(row0 + rA) * DIN + k8;
    const float* WHp = wHi + (size_t)rA * DIN + k8;
    const float* WLp = wLo + (size_t)rA * DIN + k8;
    const unsigned sb = (unsigned)__cvta_generic_to_shared(sbuf);

    auto cpw = [&](int p, int k0) {
        unsigned base = sb + (unsigned)(p * PBUF) * 4u;
        unsigned dh = base + (unsigned)(2304 + rA * 20 + k8) * 4u;
        unsigned dl = base + (unsigned)(3584 + rA * 20 + k8) * 4u;
        cp_async16(dh,      WHp + k0);
        cp_async16(dh + 16, WHp + k0 + 4);
        cp_async16(dl,      WLp + k0);
        cp_async16(dl + 16, WLp + k0 + 4);
    };

    float4 xv0 = *(const float4*)(Xp);
    float4 xv1 = *(const float4*)(Xp + 4);

    auto store_x = [&](int p) {
        float* xshp = sbuf + p * PBUF;
        float* xslp = xshp + 1152;
        const float* p0 = (const float*)&xv0;
        const float* p1 = (const float*)&xv1;
#pragma unroll
        for (int u = 0; u < 4; u++) {
            float a0 = tf32_rna(p0[u]);
            float a1 = tf32_rna(p1[u]);
            xshp[(k8 + u) * 72 + rA]     = a0;
            xslp[(k8 + u) * 72 + rA]     = tf32_rna(p0[u] - a0);
            xshp[(k8 + 4 + u) * 72 + rA] = a1;
            xslp[(k8 + 4 + u) * 72 + rA] = tf32_rna(p1[u] - a1);
        }
    };

    float acc[2][4][4];
#pragma unroll
    for (int mt = 0; mt < 2; mt++)
#pragma unroll
        for (int ct = 0; ct < 4; ct++)
#pragma unroll
            for (int m = 0; m < 4; m++) acc[mt][ct][m] = 0.f;

    cpw(0, 0); CP_COMMIT();
    store_x(0);
    CP_WAIT0();
    __syncthreads();

    for (int i = 0; i < 48; i++) {
        if (i + 1 < 48) {
            const int k0n = (i + 1) * 16;
            xv0 = *(const float4*)(Xp + k0n);
            xv1 = *(const float4*)(Xp + k0n + 4);
            cpw((i + 1) & 1, k0n); CP_COMMIT();
        }
        {
            const float* xshp = sbuf + (i & 1) * PBUF;
            const float* xslp = xshp + 1152;
            const float* wshp = xshp + 2304;
            const float* wslp = xshp + 3584;
#pragma unroll
            for (int kc = 0; kc < 2; kc++) {
                const int ks = kc * 8;
                unsigned ah[2][4], al[2][4];
#pragma unroll
                for (int mt = 0; mt < 2; mt++) {
                    const int r = mrow + mt * 16 + gid;
                    ah[mt][0] = __float_as_uint(xshp[(ks + tig) * 72 + r]);
                    ah[mt][1] = __float_as_uint(xshp[(ks + tig) * 72 + r + 8]);
                    ah[mt][2] = __float_as_uint(xshp[(ks + tig + 4) * 72 + r]);
                    ah[mt][3] = __float_as_uint(xshp[(ks + tig + 4) * 72 + r + 8]);
                    al[mt][0] = __float_as_uint(xslp[(ks + tig) * 72 + r]);
                    al[mt][1] = __float_as_uint(xslp[(ks + tig) * 72 + r + 8]);
                    al[mt][2] = __float_as_uint(xslp[(ks + tig + 4) * 72 + r]);
                    al[mt][3] = __float_as_uint(xslp[(ks + tig + 4) * 72 + r + 8]);
                }
#pragma unroll
                for (int ct = 0; ct < 4; ct++) {
                    const int cc = ncol + ct * 8 + gid;
                    unsigned bh2[2], bl2[2];
                    bh2[0] = __float_as_uint(wshp[cc * 20 + ks + tig]);
                    bh2[1] = __float_as_uint(wshp[cc * 20 + ks + tig + 4]);
                    bl2[0] = __float_as_uint(wslp[cc * 20 + ks + tig]);
                    bl2[1] = __float_as_uint(wslp[cc * 20 + ks + tig + 4]);
#pragma unroll
                    for (int mt = 0; mt < 2; mt++) {
                        mma_tf32(acc[mt][ct], ah[mt], bh2);
                        mma_tf32(acc[mt][ct], ah[mt], bl2);
                        mma_tf32(acc[mt][ct], al[mt], bh2);
                    }
                }
            }
        }
        if (i + 1 < 48) store_x((i + 1) & 1);
        CP_WAIT0();
        __syncthreads();
    }

    // epilogue: bias into psm (aliases buf0)
    {
#pragma unroll
        for (int mt = 0; mt < 2; mt++) {
            const int r = mrow + mt * 16 + gid;
#pragma unroll
            for (int ct = 0; ct < 4; ct++) {
#pragma unroll
                for (int u = 0; u < 2; u++) {
                    const int d = ncol + ct * 8 + 2 * tig + u;
                    float bias = (d < 32) ? __ldg(be + d)
                               : (d < 48) ? __ldg(bh + d - 32)
                                          : __ldg(bs + d - 48);
                    psm[r][d]     = acc[mt][ct][u]     + bias;
                    psm[r + 8][d] = acc[mt][ct][2 + u] + bias;
                }
            }
        }
    }
    __syncthreads();

    if (tid < 64) {
        const int r = tid;
        const float sc = *scale_p;
        float s2 = 0.f;
#pragma unroll
        for (int k = 0; k < 32; k++) { float v = psm[r][k]; s2 = fmaf(v, v, s2); }
        float inv = 1.0f / sqrtf(s2);
#pragma unroll
        for (int k = 0; k < 32; k++) psm[r][k] *= inv;
        float h2 = 0.f;
#pragma unroll
        for (int k = 32; k < 48; k++) { float v = psm[r][k] * sc; psm[r][k] = v; h2 = fmaf(v, v, h2); }
        float n  = fmaxf(sqrtf(h2), 1e-15f);
        float th = tanhf(n);
        float fac = th / n;
#pragma unroll
        for (int k = 32; k < 48; k++) psm[r][k] *= fac;
        psm[r][64] = th * th;                       // yn / xn
        if (is_query) psm[r][65] = 1.0f - th * th;  // beta
        float s3 = 0.f;
#pragma unroll
        for (int k = 48; k < 64; k++) { float v = psm[r][k]; s3 = fmaf(v, v, s3); }
        float inv3 = 1.0f / sqrtf(s3);
#pragma unroll
        for (int k = 48; k < 64; k++) psm[r][k] *= inv3;
    }
    __syncthreads();

    // features: hi/lo split, coalesced (64-wide rows)
    for (int i = tid; i < 64 * 64; i += 128) {
        int k = i >> 6, r = i & 63;
        float v = psm[r][k];
        float hi = tf32_rna(v);
        float lo = tf32_rna(v - hi);
        featT [(size_t)k * fstride + row0 + r] = hi;
        featLo[(size_t)k * fstride + row0 + r] = lo;
    }
    const int np = is_query ? 2 : 1;
    for (int i = tid; i < np * 64; i += 128) {
        int k = 64 + (i >> 6), r = i & 63;
        featT[(size_t)k * fstride + row0 + r] = psm[r][k];
    }
}

// ---------------------------------------------------------------------------
// Weight-MLP layer 1, split-K with register prefetch: partials -> g_part
// ---------------------------------------------------------------------------
__global__ __launch_bounds__(256) void mlpq_part_kernel(
    const float* __restrict__ X, const float* __restrict__ W1,
    float* __restrict__ part)
{
    __shared__ __align__(16) float xs[16][68];
    __shared__ __align__(16) float ws[16][36];
    const int tid = threadIdx.x;
    const int r0 = (tid >> 3) * 2;
    const int d0 = (tid & 7) * 4;
    const int row0 = blockIdx.x * 64;
    const int kc   = blockIdx.y;            // 0..5
    const int kbeg = kc * 128;
    const int lr = tid >> 2;
    const int lk = (tid & 3) * 4;

    const float* Xp = X + (size_t)(row0 + lr) * DIN + kbeg + lk;
    const float* Wp = W1 + lr * DIN + kbeg + lk;

    float4 xv = *(const float4*)(Xp);
    float4 wv = make_float4(0.f, 0.f, 0.f, 0.f);
    if (tid < 128) wv = *(const float4*)(Wp);

    float acc[2][4] = {};
    for (int kk0 = 0; kk0 < 128; kk0 += 16) {
        __syncthreads();
        xs[lk + 0][lr] = xv.x; xs[lk + 1][lr] = xv.y;
        xs[lk + 2][lr] = xv.z; xs[lk + 3][lr] = xv.w;
        if (tid < 128) {
            ws[lk + 0][lr] = wv.x; ws[lk + 1][lr] = wv.y;
            ws[lk + 2][lr] = wv.z; ws[lk + 3][lr] = wv.w;
        }
        __syncthreads();
        if (kk0 + 16 < 128) {
            xv = *(const float4*)(Xp + kk0 + 16);
            if (tid < 128) wv = *(const float4*)(Wp + kk0 + 16);
        }
#pragma unroll
        for (int kk = 0; kk < 16; kk++) {
            float a0 = xs[kk][r0];
            float a1 = xs[kk][r0 + 1];
            float4 b4 = *(const float4*)&ws[kk][d0];
            float bv[4] = {b4.x, b4.y, b4.z, b4.w};
#pragma unroll
            for (int j = 0; j < 4; j++) {
                acc[0][j] = fmaf(a0, bv[j], acc[0][j]);
                acc[1][j] = fmaf(a1, bv[j], acc[1][j]);
            }
        }
    }
    float* dst = part + (size_t)kc * NQ * 32;
#pragma unroll
    for (int i = 0; i < 2; i++)
#pragma unroll
        for (int j = 0; j < 4; j++)
            dst[(size_t)(row0 + r0 + i) * 32 + d0 + j] = acc[i][j];
}

// ---------------------------------------------------------------------------
// Weight-MLP finish: sum partials + b1, relu, layer2 + softplus -> qfT 66..68
// ---------------------------------------------------------------------------
__global__ __launch_bounds__(256) void mlpq_fin_kernel(
    const float* __restrict__ part, const float* __restrict__ b1,
    const float* __restrict__ W2, const float* __restrict__ b2,
    float* __restrict__ qfT)
{
    const int q = blockIdx.x * 256 + threadIdx.x;
    if (q >= NQ) return;
    float y[32];
#pragma unroll
    for (int d = 0; d < 32; d += 4) {
        float4 s = *(const float4*)(part + (size_t)q * 32 + d);
#pragma unroll
        for (int kc = 1; kc < 6; kc++) {
            float4 p = *(const float4*)(part + (size_t)kc * NQ * 32 + (size_t)q * 32 + d);
            s.x += p.x; s.y += p.y; s.z += p.z; s.w += p.w;
        }
        y[d]     = fmaxf(s.x + __ldg(b1 + d),     0.f);
        y[d + 1] = fmaxf(s.y + __ldg(b1 + d + 1), 0.f);
        y[d + 2] = fmaxf(s.z + __ldg(b1 + d + 2), 0.f);
        y[d + 3] = fmaxf(s.w + __ldg(b1 + d + 3), 0.f);
    }
    float z0 = b2[0], z1 = b2[1], z2 = b2[2];
#pragma unroll
    for (int k = 0; k < 32; k++) {
        z0 = fmaf(y[k], __ldg(W2 + k),      z0);
        z1 = fmaf(y[k], __ldg(W2 + 32 + k), z1);
        z2 = fmaf(y[k], __ldg(W2 + 64 + k), z2);
    }
    float sp0 = fmaxf(z0, 0.f) + log1pf(expf(-fabsf(z0)));
    float sp1 = fmaxf(z1, 0.f) + log1pf(expf(-fabsf(z1)));
    float sp2 = fmaxf(z2, 0.f) + log1pf(expf(-fabsf(z2)));
    qfT[(size_t)66 * NQ + q] = sp0;
    qfT[(size_t)67 * NQ + q] = sp1 * 0.4804530139182014f;  // fold ln2^2
    qfT[(size_t)68 * NQ + q] = sp2;
}

// ---------------------------------------------------------------------------
// Pairwise kernel: 64q x 128c per CTA, 8 warps of 32x32, tf32 MMA split hi/lo.
// Early-LDG prefetch; h-phase uses L = lg2(den+s) - lg2(den-s) (3 MUFU).
// ---------------------------------------------------------------------------
__global__ __launch_bounds__(256, 2) void pair_kernel(
    const float* __restrict__ qfT, const float* __restrict__ qfLo,
    const float* __restrict__ cfT, const float* __restrict__ cfLo,
    float* __restrict__ out)
{
    __shared__ __align__(16) float sqh[16][72], sql[16][72];
    __shared__ __align__(16) float sch[16][136], sclo[16][136];
    __shared__ float qxn[64], qbt[64], qw0[64], qw1[64], qw2[64], cyn[128];

    const int tid  = threadIdx.x;
    const int lane = tid & 31;
    const int warp = tid >> 5;
    const int gid  = lane >> 2;
    const int tig  = lane & 3;
    const int qw   = (warp >> 2) * 32;
    const int cw   = (warp & 3) * 32;

    const int q0 = blockIdx.y * 64;
    const int c0 = blockIdx.x * 128;

    const int qrow = tid >> 4;
    const int qc4  = (tid & 15) * 4;
    const int crow = tid >> 5;
    const int cc4  = (tid & 31) * 4;

    float4 pqh, pql, pch0, pcl0, pch1, pcl1;
    auto ld_stage = [&](int off) {
        pqh  = *(const float4*)(qfT  + (size_t)(off + qrow) * NQ + q0 + qc4);
        pql  = *(const float4*)(qfLo + (size_t)(off + qrow) * NQ + q0 + qc4);
        pch0 = *(const float4*)(cfT  + (size_t)(off + crow) * NC + c0 + cc4);
        pcl0 = *(const float4*)(cfLo + (size_t)(off + crow) * NC + c0 + cc4);
        pch1 = *(const float4*)(cfT  + (size_t)(off + crow + 8) * NC + c0 + cc4);
        pcl1 = *(const float4*)(cfLo + (size_t)(off + crow + 8) * NC + c0 + cc4);
    };
    auto st_stage = [&]() {
        *(float4*)&sqh[qrow][qc4]      = pqh;
        *(float4*)&sql[qrow][qc4]      = pql;
        *(float4*)&sch[crow][cc4]      = pch0;
        *(float4*)&sclo[crow][cc4]     = pcl0;
        *(float4*)&sch[crow + 8][cc4]  = pch1;
        *(float4*)&sclo[crow + 8][cc4] = pcl1;
    };

    ld_stage(0);

    if (tid < 64) {
        qxn[tid] = qfT[(size_t)64 * NQ + q0 + tid];
        qbt[tid] = qfT[(size_t)65 * NQ + q0 + tid];
        qw0[tid] = qfT[(size_t)66 * NQ + q0 + tid];
        qw1[tid] = qfT[(size_t)67 * NQ + q0 + tid];
        qw2[tid] = qfT[(size_t)68 * NQ + q0 + tid];
    } else if (tid < 192) {
        const int r = tid - 64;
        cyn[r] = cfT[(size_t)64 * NC + c0 + r];
    }

    auto seg_mma = [&](float acc[8][4]) {
#pragma unroll
        for (int kc = 0; kc < 2; kc++) {
            const int k0 = kc * 8;
            unsigned bh[4][2], bl[4][2];
#pragma unroll
            for (int ct = 0; ct < 4; ct++) {
                const int cc = cw + ct * 8 + gid;
                bh[ct][0] = __float_as_uint(sch [k0 + tig][cc]);
                bh[ct][1] = __float_as_uint(sch [k0 + tig + 4][cc]);
                bl[ct][0] = __float_as_uint(sclo[k0 + tig][cc]);
                bl[ct][1] = __float_as_uint(sclo[k0 + tig + 4][cc]);
            }
#pragma unroll
            for (int qt = 0; qt < 2; qt++) {
                const int r = qw + qt * 16 + gid;
                unsigned ah[4], al[4];
                ah[0] = __float_as_uint(sqh[k0 + tig][r]);
                ah[1] = __float_as_uint(sqh[k0 + tig][r + 8]);
                ah[2] = __float_as_uint(sqh[k0 + tig + 4][r]);
                ah[3] = __float_as_uint(sqh[k0 + tig + 4][r + 8]);
                al[0] = __float_as_uint(sql[k0 + tig][r]);
                al[1] = __float_as_uint(sql[k0 + tig][r + 8]);
                al[2] = __float_as_uint(sql[k0 + tig + 4][r]);
                al[3] = __float_as_uint(sql[k0 + tig + 4][r + 8]);
#pragma unroll
                for (int ct = 0; ct < 4; ct++) {
                    float* a = acc[qt * 4 + ct];
                    mma_tf32(a, ah, bh[ct]);
                    mma_tf32(a, ah, bl[ct]);
                    mma_tf32(a, al, bh[ct]);
                }
            }
        }
    };

    float tot[8][4];
    float acc[8][4];

    // ================= phase e (rows 0..31: two segments) =================
#pragma unroll
    for (int t = 0; t < 8; t++)
#pragma unroll
        for (int m = 0; m < 4; m++) acc[t][m] = 0.f;
    st_stage();
    __syncthreads();
    ld_stage(16);
    seg_mma(acc);
    __syncthreads();
    st_stage();
    __syncthreads();
    ld_stage(32);
    seg_mma(acc);
#pragma unroll
    for (int qt = 0; qt < 2; qt++) {
        const int lqA = qw + qt * 16 + gid;
        const float wA = qw0[lqA], wB = qw0[lqA + 8];
#pragma unroll
        for (int ct = 0; ct < 4; ct++) {
            const int t = qt * 4 + ct;
            tot[t][0] = wA * (2.f - 2.f * acc[t][0]);
            tot[t][1] = wA * (2.f - 2.f * acc[t][1]);
            tot[t][2] = wB * (2.f - 2.f * acc[t][2]);
            tot[t][3] = wB * (2.f - 2.f * acc[t][3]);
        }
    }

    // ================= phase h =================
#pragma unroll
    for (int t = 0; t < 8; t++)
#pragma unroll
        for (int m = 0; m < 4; m++) acc[t][m] = 0.f;
    __syncthreads();
    st_stage();
    __syncthreads();
    ld_stage(48);
    seg_mma(acc);
#pragma unroll
    for (int qt = 0; qt < 2; qt++) {
        const int lqA = qw + qt * 16 + gid;
#pragma unroll
        for (int half = 0; half < 2; half++) {
            const int lq = lqA + half * 8;
            const float xn = qxn[lq];
            const float bt = qbt[lq];
            const float nb = -2.f * bt;
            const float bb = bt * bt;
            const float w1 = qw1[lq];
#pragma unroll
            for (int ct = 0; ct < 4; ct++) {
                const int t = qt * 4 + ct;
                const int lc = cw + ct * 8 + 2 * tig;
#pragma unroll
                for (int m = 0; m < 2; m++) {
                    const float dh = acc[t][half * 2 + m];
                    const float yn = cyn[lc + m];
                    float s1 = fmaf(-2.f, dh, 1.f);
                    float alpha = s1 + yn;
                    float num = fmaf(alpha, fmaf(alpha, xn, nb * dh), bb * yn);
                    float den = fmaxf(fmaf(xn, yn, s1), 1e-15f);
                    float s = f_sqrt(fmaxf(num, 0.f));
                    float u = fmaxf(den - s, 6.0e-8f * den);
                    float L = f_lg2(den + s) - f_lg2(u);   // = lg2((1+t)/(1-t))
                    tot[t][half * 2 + m] = fmaf(w1, L * L, tot[t][half * 2 + m]);
                }
            }
        }
    }

    // ================= phase s =================
#pragma unroll
    for (int t = 0; t < 8; t++)
#pragma unroll
        for (int m = 0; m < 4; m++) acc[t][m] = 0.f;
    __syncthreads();
    st_stage();
    __syncthreads();
    seg_mma(acc);
#pragma unroll
    for (int qt = 0; qt < 2; qt++) {
        const int lqA = qw + qt * 16 + gid;
#pragma unroll
        for (int half = 0; half < 2; half++) {
            const int lq = lqA + half * 8;
            const float w2 = qw2[lq];
#pragma unroll
            for (int ct = 0; ct < 4; ct++) {
                const int t = qt * 4 + ct;
#pragma unroll
                for (int m = 0; m < 2; m++) {
                    const float d = acc[t][half * 2 + m];
                    float ad = fminf(fabsf(d), 1.f);
                    float sq = f_sqrt(fmaxf(1.f - ad, 0.f));
                    float p = -0.0012624911f;
                    p = fmaf(p, ad,  0.0066700901f);
                    p = fmaf(p, ad, -0.0170881256f);
                    p = fmaf(p, ad,  0.0308918810f);
                    p = fmaf(p, ad, -0.0501743046f);
                    p = fmaf(p, ad,  0.0889789874f);
                    p = fmaf(p, ad, -0.2145988016f);
                    p = fmaf(p, ad,  1.5707963050f);
                    float r = sq * p;
                    float a = (d >= 0.f) ? r : 3.14159265358979f - r;
                    tot[t][half * 2 + m] = fmaf(w2, a * a, tot[t][half * 2 + m]);
                }
            }
        }
    }

    // ================= store -total =================
#pragma unroll
    for (int qt = 0; qt < 2; qt++) {
        const int lqA = qw + qt * 16 + gid;
#pragma unroll
        for (int ct = 0; ct < 4; ct++) {
            const int t = qt * 4 + ct;
            const int lc = cw + ct * 8 + 2 * tig;
            float2 oA = make_float2(-tot[t][0], -tot[t][1]);
            float2 oB = make_float2(-tot[t][2], -tot[t][3]);
            *(float2*)(out + (size_t)(q0 + lqA) * NC + c0 + lc)     = oA;
            *(float2*)(out + (size_t)(q0 + lqA + 8) * NC + c0 + lc) = oB;
        }
    }
}

// ---------------------------------------------------------------------------
extern "C" void kernel_launch(void* const* d_in, const int* in_sizes, int n_in,
                              void* d_out, int out_size)
{
    const float* x_q  = (const float*)d_in[0];
    const float* x_c  = (const float*)d_in[1];
    const float* We   = (const float*)d_in[2];
    const float* be   = (const float*)d_in[3];
    const float* Wh   = (const float*)d_in[4];
    const float* bh   = (const float*)d_in[5];
    const float* Ws   = (const float*)d_in[6];
    const float* bs   = (const float*)d_in[7];
    const float* scl  = (const float*)d_in[8];
    const float* W1   = (const float*)d_in[9];
    const float* b1   = (const float*)d_in[10];
    const float* W2   = (const float*)d_in[11];
    const float* b2   = (const float*)d_in[12];
    float* out = (float*)d_out;

    float *cfT, *cfLo, *qfT, *qfLo, *wHi, *wLo, *part;
    cudaGetSymbolAddress((void**)&cfT,  g_cfeatT);
    cudaGetSymbolAddress((void**)&cfLo, g_cfeatLo);
    cudaGetSymbolAddress((void**)&qfT,  g_qfeatT);
    cudaGetSymbolAddress((void**)&qfLo, g_qfeatLo);
    cudaGetSymbolAddress((void**)&wHi,  g_wHi);
    cudaGetSymbolAddress((void**)&wLo,  g_wLo);
    cudaGetSymbolAddress((void**)&part, g_part);

    wsplit_kernel<<<(64 * DIN + 255) / 256, 256>>>(We, Wh, Ws, wHi, wLo);
    projmma_kernel<<<NC / 64, 128>>>(x_c, be, bh, bs, scl, wHi, wLo, cfT, cfLo, NC, 0);
    projmma_kernel<<<NQ / 64, 128>>>(x_q, be, bh, bs, scl, wHi, wLo, qfT, qfLo, NQ, 1);
    mlpq_part_kernel<<<dim3(NQ / 64, 6), 256>>>(x_q, W1, part);
    mlpq_fin_kernel<<<NQ / 256, 256>>>(part, b1, W2, b2, qfT);
    pair_kernel<<<dim3(NC / 128, NQ / 64), 256>>>(qfT, qfLo, cfT, cfLo, out);
}

// round 15
// speedup vs baseline: 1.9606x; 1.0468x over previous
#include <cuda_runtime.h>
#include <math.h>

#define NQ 512
#define NC 65536
#define DIN 768

// Scratch (static device globals).
__device__ float g_cfeatT[66 * NC];    // corpus: 0..63 hi, 64 = yn, 65 = 1/(1-yn)
__device__ float g_cfeatLo[64 * NC];
__device__ float g_qfeatT[69 * NQ];    // query: 0..63 hi, 64 xn, 65 2/(1-xn), 66 w0, 67 w1*ln2^2, 68 w2
__device__ float g_qfeatLo[64 * NQ];
__device__ float g_wHi[64 * DIN];      // concatenated We/Wh/Ws tf32 hi
__device__ float g_wLo[64 * DIN];      // ... lo residual
__device__ float g_part[6 * NQ * 32];  // mlp split-K partials

// ---------------- helpers ----------------
__device__ __forceinline__ float f_sqrt(float x) { float r; asm("sqrt.approx.f32 %0,%1;" : "=f"(r) : "f"(x)); return r; }
__device__ __forceinline__ float f_lg2(float x)  { float r; asm("lg2.approx.f32 %0,%1;"  : "=f"(r) : "f"(x)); return r; }
__device__ __forceinline__ float tf32_rna(float x) {
    unsigned u; asm("cvt.rna.tf32.f32 %0,%1;" : "=r"(u) : "f"(x)); return __uint_as_float(u);
}
__device__ __forceinline__ void mma_tf32(float c[4], const unsigned a[4], const unsigned b[2]) {
    asm volatile(
        "mma.sync.aligned.m16n8k8.row.col.f32.tf32.tf32.f32 "
        "{%0,%1,%2,%3},{%4,%5,%6,%7},{%8,%9},{%0,%1,%2,%3};"
        : "+f"(c[0]), "+f"(c[1]), "+f"(c[2]), "+f"(c[3])
        : "r"(a[0]), "r"(a[1]), "r"(a[2]), "r"(a[3]), "r"(b[0]), "r"(b[1]));
}
__device__ __forceinline__ void cp_async16(unsigned dst, const void* src) {
    asm volatile("cp.async.cg.shared.global [%0], [%1], 16;" :: "r"(dst), "l"(src) : "memory");
}
#define CP_COMMIT() asm volatile("cp.async.commit_group;" ::: "memory")
#define CP_WAIT0()  asm volatile("cp.async.wait_group 0;" ::: "memory")

// ---------------------------------------------------------------------------
// One-time W split: concatenated [64][768] tf32 hi/lo planes
// ---------------------------------------------------------------------------
__global__ void wsplit_kernel(const float* __restrict__ We,
                              const float* __restrict__ Wh,
                              const float* __restrict__ Ws,
                              float* __restrict__ wHi, float* __restrict__ wLo)
{
    int i = blockIdx.x * 256 + threadIdx.x;
    if (i >= 64 * DIN) return;
    int d = i / DIN;
    int k = i - d * DIN;
    float v = (d < 32) ? We[d * DIN + k]
            : (d < 48) ? Wh[(d - 32) * DIN + k]
                       : Ws[(d - 48) * DIN + k];
    float hi = tf32_rna(v);
    wHi[i] = hi;
    wLo[i] = tf32_rna(v - hi);
}

// ---------------------------------------------------------------------------
// Projection (tf32 MMA v6): 64 rows x 64 dims per CTA, 128 threads (4 warps),
// 2x2 warp layout, ping-pong. X staged RAW via cp.async ([64][20] row-major);
// hi/lo split happens in the fragment load (bitwise-identical MMA inputs).
// Buffer (floats): xr 0..1279 [64][20], wsh 1280 [64][20], wsl 2560; PBUF=3840.
// 6 CTAs/SM.
// ---------------------------------------------------------------------------
#define PBUF 3840

__global__ __launch_bounds__(128, 6) void projmma_kernel(
    const float* __restrict__ X,
    const float* __restrict__ be, const float* __restrict__ bh,
    const float* __restrict__ bs, const float* __restrict__ scale_p,
    const float* __restrict__ wHi, const float* __restrict__ wLo,
    float* __restrict__ featT, float* __restrict__ featLo,
    int fstride, int is_query)
{
    __shared__ __align__(16) float sbuf[2 * PBUF];       // 30.7 KB
    float (*psm)[69] = (float(*)[69])(sbuf);             // 64 x 69 (aliases)

    const int tid  = threadIdx.x;
    const int lane = tid & 31;
    const int warp = tid >> 5;
    const int gid  = lane >> 2;
    const int tig  = lane & 3;
    const int mrow = (warp & 1) * 32;
    const int ncol = (warp >> 1) * 32;
    const int row0 = blockIdx.x * 64;

    const int rA = tid >> 1;         // 0..63
    const int k8 = (tid & 1) * 8;    // 0 or 8

    const float* Xp  = X   + (size_t)(row0 + rA) * DIN + k8;
    const float* WHp = wHi + (size_t)rA * DIN + k8;
    const float* WLp = wLo + (size_t)rA * DIN + k8;
    const unsigned sb = (unsigned)__cvta_generic_to_shared(sbuf);

    auto cpall = [&](int p, int k0) {
        unsigned base = sb + (unsigned)(p * PBUF) * 4u;
        unsigned dx = base + (unsigned)(rA * 20 + k8) * 4u;
        cp_async16(dx,      Xp + k0);
        cp_async16(dx + 16, Xp + k0 + 4);
        unsigned dh = base + (unsigned)(1280 + rA * 20 + k8) * 4u;
        cp_async16(dh,      WHp + k0);
        cp_async16(dh + 16, WHp + k0 + 4);
        unsigned dl = base + (unsigned)(2560 + rA * 20 + k8) * 4u;
        cp_async16(dl,      WLp + k0);
        cp_async16(dl + 16, WLp + k0 + 4);
    };

    float acc[2][4][4];
#pragma unroll
    for (int mt = 0; mt < 2; mt++)
#pragma unroll
        for (int ct = 0; ct < 4; ct++)
#pragma unroll
            for (int m = 0; m < 4; m++) acc[mt][ct][m] = 0.f;

    cpall(0, 0); CP_COMMIT();
    CP_WAIT0();
    __syncthreads();

    for (int i = 0; i < 48; i++) {
        if (i + 1 < 48) {
            cpall((i + 1) & 1, (i + 1) * 16); CP_COMMIT();
        }
        {
            const float* xr   = sbuf + (i & 1) * PBUF;
            const float* wshp = xr + 1280;
            const float* wslp = xr + 2560;
#pragma unroll
            for (int kc = 0; kc < 2; kc++) {
                const int ks = kc * 8;
                unsigned ah[2][4], al[2][4];
#pragma unroll
                for (int mt = 0; mt < 2; mt++) {
                    const int r = mrow + mt * 16 + gid;
                    float raw[4];
                    raw[0] = xr[r * 20 + ks + tig];
                    raw[1] = xr[(r + 8) * 20 + ks + tig];
                    raw[2] = xr[r * 20 + ks + tig + 4];
                    raw[3] = xr[(r + 8) * 20 + ks + tig + 4];
#pragma unroll
                    for (int u = 0; u < 4; u++) {
                        float hi = tf32_rna(raw[u]);
                        ah[mt][u] = __float_as_uint(hi);
                        al[mt][u] = __float_as_uint(tf32_rna(raw[u] - hi));
                    }
                }
#pragma unroll
                for (int ct = 0; ct < 4; ct++) {
                    const int cc = ncol + ct * 8 + gid;
                    unsigned bh2[2], bl2[2];
                    bh2[0] = __float_as_uint(wshp[cc * 20 + ks + tig]);
                    bh2[1] = __float_as_uint(wshp[cc * 20 + ks + tig + 4]);
                    bl2[0] = __float_as_uint(wslp[cc * 20 + ks + tig]);
                    bl2[1] = __float_as_uint(wslp[cc * 20 + ks + tig + 4]);
#pragma unroll
                    for (int mt = 0; mt < 2; mt++) {
                        mma_tf32(acc[mt][ct], ah[mt], bh2);
                        mma_tf32(acc[mt][ct], ah[mt], bl2);
                        mma_tf32(acc[mt][ct], al[mt], bh2);
                    }
                }
            }
        }
        CP_WAIT0();
        __syncthreads();
    }

    // epilogue: bias into psm (aliases staging)
    {
#pragma unroll
        for (int mt = 0; mt < 2; mt++) {
            const int r = mrow + mt * 16 + gid;
#pragma unroll
            for (int ct = 0; ct < 4; ct++) {
#pragma unroll
                for (int u = 0; u < 2; u++) {
                    const int d = ncol + ct * 8 + 2 * tig + u;
                    float bias = (d < 32) ? __ldg(be + d)
                               : (d < 48) ? __ldg(bh + d - 32)
                                          : __ldg(bs + d - 48);
                    psm[r][d]     = acc[mt][ct][u]     + bias;
                    psm[r + 8][d] = acc[mt][ct][2 + u] + bias;
                }
            }
        }
    }
    __syncthreads();

    if (tid < 64) {
        const int r = tid;
        const float sc = *scale_p;
        float s2 = 0.f;
#pragma unroll
        for (int k = 0; k < 32; k++) { float v = psm[r][k]; s2 = fmaf(v, v, s2); }
        float inv = 1.0f / sqrtf(s2);
#pragma unroll
        for (int k = 0; k < 32; k++) psm[r][k] *= inv;
        float h2 = 0.f;
#pragma unroll
        for (int k = 32; k < 48; k++) { float v = psm[r][k] * sc; psm[r][k] = v; h2 = fmaf(v, v, h2); }
        float n  = fmaxf(sqrtf(h2), 1e-15f);
        float th = tanhf(n);
        float fac = th / n;
#pragma unroll
        for (int k = 32; k < 48; k++) psm[r][k] *= fac;
        float nn = th * th;
        psm[r][64] = nn;                                     // yn / xn
        psm[r][65] = (is_query ? 2.0f : 1.0f) / (1.0f - nn); // 2/(1-xn) or 1/(1-yn)
        float s3 = 0.f;
#pragma unroll
        for (int k = 48; k < 64; k++) { float v = psm[r][k]; s3 = fmaf(v, v, s3); }
        float inv3 = 1.0f / sqrtf(s3);
#pragma unroll
        for (int k = 48; k < 64; k++) psm[r][k] *= inv3;
    }
    __syncthreads();

    // features: hi/lo split, coalesced
    for (int i = tid; i < 64 * 64; i += 128) {
        int k = i >> 6, r = i & 63;
        float v = psm[r][k];
        float hi = tf32_rna(v);
        float lo = tf32_rna(v - hi);
        featT [(size_t)k * fstride + row0 + r] = hi;
        featLo[(size_t)k * fstride + row0 + r] = lo;
    }
    for (int i = tid; i < 2 * 64; i += 128) {
        int k = 64 + (i >> 6), r = i & 63;
        featT[(size_t)k * fstride + row0 + r] = psm[r][k];
    }
}

// ---------------------------------------------------------------------------
// Weight-MLP layer 1, split-K with register prefetch: partials -> g_part
// ---------------------------------------------------------------------------
__global__ __launch_bounds__(256) void mlpq_part_kernel(
    const float* __restrict__ X, const float* __restrict__ W1,
    float* __restrict__ part)
{
    __shared__ __align__(16) float xs[16][68];
    __shared__ __align__(16) float ws[16][36];
    const int tid = threadIdx.x;
    const int r0 = (tid >> 3) * 2;
    const int d0 = (tid & 7) * 4;
    const int row0 = blockIdx.x * 64;
    const int kc   = blockIdx.y;            // 0..5
    const int kbeg = kc * 128;
    const int lr = tid >> 2;
    const int lk = (tid & 3) * 4;

    const float* Xp = X + (size_t)(row0 + lr) * DIN + kbeg + lk;
    const float* Wp = W1 + lr * DIN + kbeg + lk;

    float4 xv = *(const float4*)(Xp);
    float4 wv = make_float4(0.f, 0.f, 0.f, 0.f);
    if (tid < 128) wv = *(const float4*)(Wp);

    float acc[2][4] = {};
    for (int kk0 = 0; kk0 < 128; kk0 += 16) {
        __syncthreads();
        xs[lk + 0][lr] = xv.x; xs[lk + 1][lr] = xv.y;
        xs[lk + 2][lr] = xv.z; xs[lk + 3][lr] = xv.w;
        if (tid < 128) {
            ws[lk + 0][lr] = wv.x; ws[lk + 1][lr] = wv.y;
            ws[lk + 2][lr] = wv.z; ws[lk + 3][lr] = wv.w;
        }
        __syncthreads();
        if (kk0 + 16 < 128) {
            xv = *(const float4*)(Xp + kk0 + 16);
            if (tid < 128) wv = *(const float4*)(Wp + kk0 + 16);
        }
#pragma unroll
        for (int kk = 0; kk < 16; kk++) {
            float a0 = xs[kk][r0];
            float a1 = xs[kk][r0 + 1];
            float4 b4 = *(const float4*)&ws[kk][d0];
            float bv[4] = {b4.x, b4.y, b4.z, b4.w};
#pragma unroll
            for (int j = 0; j < 4; j++) {
                acc[0][j] = fmaf(a0, bv[j], acc[0][j]);
                acc[1][j] = fmaf(a1, bv[j], acc[1][j]);
            }
        }
    }
    float* dst = part + (size_t)kc * NQ * 32;
#pragma unroll
    for (int i = 0; i < 2; i++)
#pragma unroll
        for (int j = 0; j < 4; j++)
            dst[(size_t)(row0 + r0 + i) * 32 + d0 + j] = acc[i][j];
}

// ---------------------------------------------------------------------------
// Weight-MLP finish: sum partials + b1, relu, layer2 + softplus -> qfT 66..68
// ---------------------------------------------------------------------------
__global__ __launch_bounds__(256) void mlpq_fin_kernel(
    const float* __restrict__ part, const float* __restrict__ b1,
    const float* __restrict__ W2, const float* __restrict__ b2,
    float* __restrict__ qfT)
{
    const int q = blockIdx.x * 256 + threadIdx.x;
    if (q >= NQ) return;
    float y[32];
#pragma unroll
    for (int d = 0; d < 32; d += 4) {
        float4 s = *(const float4*)(part + (size_t)q * 32 + d);
#pragma unroll
        for (int kc = 1; kc < 6; kc++) {
            float4 p = *(const float4*)(part + (size_t)kc * NQ * 32 + (size_t)q * 32 + d);
            s.x += p.x; s.y += p.y; s.z += p.z; s.w += p.w;
        }
        y[d]     = fmaxf(s.x + __ldg(b1 + d),     0.f);
        y[d + 1] = fmaxf(s.y + __ldg(b1 + d + 1), 0.f);
        y[d + 2] = fmaxf(s.z + __ldg(b1 + d + 2), 0.f);
        y[d + 3] = fmaxf(s.w + __ldg(b1 + d + 3), 0.f);
    }
    float z0 = b2[0], z1 = b2[1], z2 = b2[2];
#pragma unroll
    for (int k = 0; k < 32; k++) {
        z0 = fmaf(y[k], __ldg(W2 + k),      z0);
        z1 = fmaf(y[k], __ldg(W2 + 32 + k), z1);
        z2 = fmaf(y[k], __ldg(W2 + 64 + k), z2);
    }
    float sp0 = fmaxf(z0, 0.f) + log1pf(expf(-fabsf(z0)));
    float sp1 = fmaxf(z1, 0.f) + log1pf(expf(-fabsf(z1)));
    float sp2 = fmaxf(z2, 0.f) + log1pf(expf(-fabsf(z2)));
    qfT[(size_t)66 * NQ + q] = sp0;
    qfT[(size_t)67 * NQ + q] = sp1 * 0.4804530139182014f;  // fold ln2^2 (d = ln2*lg2)
    qfT[(size_t)68 * NQ + q] = sp2;
}

// ---------------------------------------------------------------------------
// Pairwise kernel: 64q x 128c per CTA, 8 warps of 32x32, tf32 MMA split hi/lo.
// Double-buffered staging (4 syncs). h-phase via acosh identity (2 MUFU):
//   d = acosh(1 + (xn+yn-2dot) * (2/(1-xn)) * (1/(1-yn)))
// Stage buffer (floats): sqh 0 [16][72], sql 1152, sch 2304 [16][136],
// sclo 4480; BUFSZ=6656.
// ---------------------------------------------------------------------------
#define BUFSZ 6656

__global__ __launch_bounds__(256, 2) void pair_kernel(
    const float* __restrict__ qfT, const float* __restrict__ qfLo,
    const float* __restrict__ cfT, const float* __restrict__ cfLo,
    float* __restrict__ out)
{
    __shared__ __align__(16) float sstage[2 * BUFSZ];    // 53.2 KB
    __shared__ float qxn[64], qib2[64], qw0[64], qw1[64], qw2[64];
    __shared__ float cyn[128], cig[128];

    const int tid  = threadIdx.x;
    const int lane = tid & 31;
    const int warp = tid >> 5;
    const int gid  = lane >> 2;
    const int tig  = lane & 3;
    const int qw   = (warp >> 2) * 32;
    const int cw   = (warp & 3) * 32;

    const int q0 = blockIdx.y * 64;
    const int c0 = blockIdx.x * 128;

    const int qrow = tid >> 4;
    const int qc4  = (tid & 15) * 4;
    const int crow = tid >> 5;
    const int cc4  = (tid & 31) * 4;

    float4 pqh, pql, pch0, pcl0, pch1, pcl1;
    auto ld_stage = [&](int off) {
        pqh  = *(const float4*)(qfT  + (size_t)(off + qrow) * NQ + q0 + qc4);
        pql  = *(const float4*)(qfLo + (size_t)(off + qrow) * NQ + q0 + qc4);
        pch0 = *(const float4*)(cfT  + (size_t)(off + crow) * NC + c0 + cc4);
        pcl0 = *(const float4*)(cfLo + (size_t)(off + crow) * NC + c0 + cc4);
        pch1 = *(const float4*)(cfT  + (size_t)(off + crow + 8) * NC + c0 + cc4);
        pcl1 = *(const float4*)(cfLo + (size_t)(off + crow + 8) * NC + c0 + cc4);
    };
    auto st_stage = [&](int p) {
        float* B = sstage + p * BUFSZ;
        *(float4*)&B[qrow * 72 + qc4]               = pqh;
        *(float4*)&B[1152 + qrow * 72 + qc4]        = pql;
        *(float4*)&B[2304 + crow * 136 + cc4]       = pch0;
        *(float4*)&B[4480 + crow * 136 + cc4]       = pcl0;
        *(float4*)&B[2304 + (crow + 8) * 136 + cc4] = pch1;
        *(float4*)&B[4480 + (crow + 8) * 136 + cc4] = pcl1;
    };

    ld_stage(0);

    if (tid < 64) {
        qxn[tid]  = qfT[(size_t)64 * NQ + q0 + tid];
        qib2[tid] = qfT[(size_t)65 * NQ + q0 + tid];
        qw0[tid]  = qfT[(size_t)66 * NQ + q0 + tid];
        qw1[tid]  = qfT[(size_t)67 * NQ + q0 + tid];
        qw2[tid]  = qfT[(size_t)68 * NQ + q0 + tid];
    } else if (tid < 192) {
        const int r = tid - 64;
        cyn[r] = cfT[(size_t)64 * NC + c0 + r];
    } else {
        const int r = tid - 192;
        cig[r]      = cfT[(size_t)65 * NC + c0 + r];
        cig[r + 64] = cfT[(size_t)65 * NC + c0 + r + 64];
    }

    auto seg_mma = [&](int p, float acc[8][4]) {
        const float* B    = sstage + p * BUFSZ;
        const float* sqh_ = B;
        const float* sql_ = B + 1152;
        const float* sch_ = B + 2304;
        const float* scl_ = B + 4480;
#pragma unroll
        for (int kc = 0; kc < 2; kc++) {
            const int k0 = kc * 8;
            unsigned bh[4][2], bl[4][2];
#pragma unroll
            for (int ct = 0; ct < 4; ct++) {
                const int cc = cw + ct * 8 + gid;
                bh[ct][0] = __float_as_uint(sch_[(k0 + tig) * 136 + cc]);
                bh[ct][1] = __float_as_uint(sch_[(k0 + tig + 4) * 136 + cc]);
                bl[ct][0] = __float_as_uint(scl_[(k0 + tig) * 136 + cc]);
                bl[ct][1] = __float_as_uint(scl_[(k0 + tig + 4) * 136 + cc]);
            }
#pragma unroll
            for (int qt = 0; qt < 2; qt++) {
                const int r = qw + qt * 16 + gid;
                unsigned ah[4], al[4];
                ah[0] = __float_as_uint(sqh_[(k0 + tig) * 72 + r]);
                ah[1] = __float_as_uint(sqh_[(k0 + tig) * 72 + r + 8]);
                ah[2] = __float_as_uint(sqh_[(k0 + tig + 4) * 72 + r]);
                ah[3] = __float_as_uint(sqh_[(k0 + tig + 4) * 72 + r + 8]);
                al[0] = __float_as_uint(sql_[(k0 + tig) * 72 + r]);
                al[1] = __float_as_uint(sql_[(k0 + tig) * 72 + r + 8]);
                al[2] = __float_as_uint(sql_[(k0 + tig + 4) * 72 + r]);
                al[3] = __float_as_uint(sql_[(k0 + tig + 4) * 72 + r + 8]);
#pragma unroll
                for (int ct = 0; ct < 4; ct++) {
                    float* a = acc[qt * 4 + ct];
                    mma_tf32(a, ah, bh[ct]);
                    mma_tf32(a, ah, bl[ct]);
                    mma_tf32(a, al, bh[ct]);
                }
            }
        }
    };

    float tot[8][4];
    float acc[8][4];

    // ---- pipeline: stage S0, then 1 sync per segment ----
    st_stage(0);
    __syncthreads();

    // e part 1 (rows 0..15) from S0
#pragma unroll
    for (int t = 0; t < 8; t++)
#pragma unroll
        for (int m = 0; m < 4; m++) acc[t][m] = 0.f;
    ld_stage(16);
    seg_mma(0, acc);
    st_stage(1);
    __syncthreads();

    // e part 2 (rows 16..31) from S1
    ld_stage(32);
    seg_mma(1, acc);
    st_stage(0);
    __syncthreads();

    // epilogue e
#pragma unroll
    for (int qt = 0; qt < 2; qt++) {
        const int lqA = qw + qt * 16 + gid;
        const float wA = qw0[lqA], wB = qw0[lqA + 8];
#pragma unroll
        for (int ct = 0; ct < 4; ct++) {
            const int t = qt * 4 + ct;
            tot[t][0] = wA * (2.f - 2.f * acc[t][0]);
            tot[t][1] = wA * (2.f - 2.f * acc[t][1]);
            tot[t][2] = wB * (2.f - 2.f * acc[t][2]);
            tot[t][3] = wB * (2.f - 2.f * acc[t][3]);
        }
    }

    // h (rows 32..47) from S0
#pragma unroll
    for (int t = 0; t < 8; t++)
#pragma unroll
        for (int m = 0; m < 4; m++) acc[t][m] = 0.f;
    ld_stage(48);
    seg_mma(0, acc);
    st_stage(1);
    __syncthreads();

    // epilogue h: acosh identity, 2 MUFU per output
#pragma unroll
    for (int qt = 0; qt < 2; qt++) {
        const int lqA = qw + qt * 16 + gid;
#pragma unroll
        for (int half = 0; half < 2; half++) {
            const int lq = lqA + half * 8;
            const float xn  = qxn[lq];
            const float ib2 = qib2[lq];
            const float w1  = qw1[lq];
#pragma unroll
            for (int ct = 0; ct < 4; ct++) {
                const int t = qt * 4 + ct;
                const int lc = cw + ct * 8 + 2 * tig;
#pragma unroll
                for (int m = 0; m < 2; m++) {
                    const float dh = acc[t][half * 2 + m];
                    const float yn = cyn[lc + m];
                    const float ig = cig[lc + m];
                    float delta = fmaf(-2.f, dh, xn + yn);   // ||x-y||^2
                    float iv = ib2 * ig;                     // 2/((1-xn)(1-yn))
                    float z = fmaxf(fmaf(delta, iv, 1.f), 1.f);
                    float zm = fmaf(z, z, -1.f);
                    float s = f_sqrt(fmaxf(zm, 0.f));
                    float L = f_lg2(z + s);                  // acosh(z)/ln2
                    tot[t][half * 2 + m] = fmaf(w1, L * L, tot[t][half * 2 + m]);
                }
            }
        }
    }

    // s (rows 48..63) from S1
#pragma unroll
    for (int t = 0; t < 8; t++)
#pragma unroll
        for (int m = 0; m < 4; m++) acc[t][m] = 0.f;
    seg_mma(1, acc);

    // epilogue s
#pragma unroll
    for (int qt = 0; qt < 2; qt++) {
        const int lqA = qw + qt * 16 + gid;
#pragma unroll
        for (int half = 0; half < 2; half++) {
            const int lq = lqA + half * 8;
            const float w2 = qw2[lq];
#pragma unroll
            for (int ct = 0; ct < 4; ct++) {
                const int t = qt * 4 + ct;
#pragma unroll
                for (int m = 0; m < 2; m++) {
                    const float d = acc[t][half * 2 + m];
                    float ad = fminf(fabsf(d), 1.f);
                    float sq = f_sqrt(fmaxf(1.f - ad, 0.f));
                    float p = -0.0012624911f;
                    p = fmaf(p, ad,  0.0066700901f);
                    p = fmaf(p, ad, -0.0170881256f);
                    p = fmaf(p, ad,  0.0308918810f);
                    p = fmaf(p, ad, -0.0501743046f);
                    p = fmaf(p, ad,  0.0889789874f);
                    p = fmaf(p, ad, -0.2145988016f);
                    p = fmaf(p, ad,  1.5707963050f);
                    float r = sq * p;
                    float a = (d >= 0.f) ? r : 3.14159265358979f - r;
                    tot[t][half * 2 + m] = fmaf(w2, a * a, tot[t][half * 2 + m]);
                }
            }
        }
    }

    // ---- store -total ----
#pragma unroll
    for (int qt = 0; qt < 2; qt++) {
        const int lqA = qw + qt * 16 + gid;
#pragma unroll
        for (int ct = 0; ct < 4; ct++) {
            const int t = qt * 4 + ct;
            const int lc = cw + ct * 8 + 2 * tig;
            float2 oA = make_float2(-tot[t][0], -tot[t][1]);
            float2 oB = make_float2(-tot[t][2], -tot[t][3]);
            *(float2*)(out + (size_t)(q0 + lqA) * NC + c0 + lc)     = oA;
            *(float2*)(out + (size_t)(q0 + lqA + 8) * NC + c0 + lc) = oB;
        }
    }
}

// ---------------------------------------------------------------------------
extern "C" void kernel_launch(void* const* d_in, const int* in_sizes, int n_in,
                              void* d_out, int out_size)
{
    const float* x_q  = (const float*)d_in[0];
    const float* x_c  = (const float*)d_in[1];
    const float* We   = (const float*)d_in[2];
    const float* be   = (const float*)d_in[3];
    const float* Wh   = (const float*)d_in[4];
    const float* bh   = (const float*)d_in[5];
    const float* Ws   = (const float*)d_in[6];
    const float* bs   = (const float*)d_in[7];
    const float* scl  = (const float*)d_in[8];
    const float* W1   = (const float*)d_in[9];
    const float* b1   = (const float*)d_in[10];
    const float* W2   = (const float*)d_in[11];
    const float* b2   = (const float*)d_in[12];
    float* out = (float*)d_out;

    float *cfT, *cfLo, *qfT, *qfLo, *wHi, *wLo, *part;
    cudaGetSymbolAddress((void**)&cfT,  g_cfeatT);
    cudaGetSymbolAddress((void**)&cfLo, g_cfeatLo);
    cudaGetSymbolAddress((void**)&qfT,  g_qfeatT);
    cudaGetSymbolAddress((void**)&qfLo, g_qfeatLo);
    cudaGetSymbolAddress((void**)&wHi,  g_wHi);
    cudaGetSymbolAddress((void**)&wLo,  g_wLo);
    cudaGetSymbolAddress((void**)&part, g_part);

    wsplit_kernel<<<(64 * DIN + 255) / 256, 256>>>(We, Wh, Ws, wHi, wLo);
    projmma_kernel<<<NC / 64, 128>>>(x_c, be, bh, bs, scl, wHi, wLo, cfT, cfLo, NC, 0);
    projmma_kernel<<<NQ / 64, 128>>>(x_q, be, bh, bs, scl, wHi, wLo, qfT, qfLo, NQ, 1);
    mlpq_part_kernel<<<dim3(NQ / 64, 6), 256>>>(x_q, W1, part);
    mlpq_fin_kernel<<<NQ / 256, 256>>>(part, b1, W2, b2, qfT);
    pair_kernel<<<dim3(NC / 128, NQ / 64), 256>>>(qfT, qfLo, cfT, cfLo, out);
}